// round 1
// baseline (speedup 1.0000x reference)
#include <cuda_runtime.h>
#include <cuda_bf16.h>
#include <math.h>

// ---------------- problem constants ----------------
#define N1 160000
#define N2 40000
#define N3 10000
#define E1 800000
#define E2 200000
#define D1 256          // H1*HID
#define D2 64           // OUT
#define NEG_SLOPE 0.2f
#define BN_EPS 1e-5f
#define SM_EPS 1e-16f
#define FULLM 0xFFFFFFFFu

// ---------------- device scratch (allocation-free) ----------------
__device__ float g_xl1[(size_t)N1 * D1];   // 163.8 MB
__device__ float g_xr1[(size_t)N2 * D1];   // 41 MB
__device__ float g_h  [(size_t)N2 * D1];   // 41 MB   (layer1 out, BN+relu in place)
__device__ float g_xl2[(size_t)N2 * D2];   // 10.2 MB
__device__ float g_xr2[(size_t)N3 * D2];   // 2.6 MB

__device__ int g_cnt1[N2];
__device__ int g_rp1 [N2 + 1];
__device__ int g_cur1[N2];
__device__ int g_csr1[E1];

__device__ int g_cnt2[N3];
__device__ int g_rp2 [N3 + 1];
__device__ int g_cur2[N3];
__device__ int g_csr2[E2];

__device__ float g_bn_sum[D1];
__device__ float g_bn_sqs[D1];
__device__ float g_bn_scale[D1];
__device__ float g_bn_shift[D1];

__device__ __forceinline__ float lrelu(float v) { return v > 0.f ? v : NEG_SLOPE * v; }

// ---------------- CSR build ----------------
__global__ void zero_kernel() {
    int i = blockIdx.x * blockDim.x + threadIdx.x;
    if (i < N2) g_cnt1[i] = 0;
    if (i < N3) g_cnt2[i] = 0;
    if (i < D1) { g_bn_sum[i] = 0.f; g_bn_sqs[i] = 0.f; }
}

__global__ void hist_kernel(const int* __restrict__ d1, const int* __restrict__ d2) {
    int i = blockIdx.x * blockDim.x + threadIdx.x;
    if (i < E1) atomicAdd(&g_cnt1[d1[i]], 1);
    if (i < E2) atomicAdd(&g_cnt2[d2[i]], 1);
}

// single-block exclusive scan (n up to 40000): which=0 -> layer1, which=1 -> layer2
__global__ void scan_kernel(int which) {
    const int* cnt = which ? g_cnt2 : g_cnt1;
    int* rp  = which ? g_rp2  : g_rp1;
    int* cur = which ? g_cur2 : g_cur1;
    int n    = which ? N3     : N2;

    __shared__ int sh[1024];
    __shared__ int carry_sh;
    int tid = threadIdx.x;
    if (tid == 0) carry_sh = 0;
    __syncthreads();
    for (int base = 0; base < n; base += 1024) {
        int i = base + tid;
        int v = (i < n) ? cnt[i] : 0;
        sh[tid] = v;
        __syncthreads();
        #pragma unroll
        for (int off = 1; off < 1024; off <<= 1) {
            int t = (tid >= off) ? sh[tid - off] : 0;
            __syncthreads();
            sh[tid] += t;
            __syncthreads();
        }
        int carry = carry_sh;
        if (i < n) { int excl = carry + sh[tid] - v; rp[i] = excl; cur[i] = excl; }
        __syncthreads();
        if (tid == 0) carry_sh = carry + sh[1023];
        __syncthreads();
    }
    if (tid == 0) rp[n] = carry_sh;
}

__global__ void scatter_kernel(const int* __restrict__ src, const int* __restrict__ dst,
                               int E, int which) {
    int e = blockIdx.x * blockDim.x + threadIdx.x;
    if (e >= E) return;
    int d = dst[e];
    if (which) { int p = atomicAdd(&g_cur2[d], 1); g_csr2[p] = src[e]; }
    else       { int p = atomicAdd(&g_cur1[d], 1); g_csr1[p] = src[e]; }
}

// ---------------- fp32 SIMT GEMM: C[M,N] = A[M,K] @ B[K,N] + bias[N] ----------------
// BM=128, BN=64, BK=16, 256 threads, 8x4 microtile. K % 16 == 0, N % 64 == 0.
__global__ __launch_bounds__(256) void gemm_bias_kernel(
    const float* __restrict__ A, const float* __restrict__ B,
    const float* __restrict__ bias, float* __restrict__ C,
    int M, int N, int K)
{
    __shared__ float As[16][132];
    __shared__ float Bs[16][64];
    int bm = blockIdx.y * 128;
    int bn = blockIdx.x * 64;
    int tid = threadIdx.x;
    int tx = tid & 15;          // 0..15 -> 4 cols each
    int ty = tid >> 4;          // 0..15 -> 8 rows each
    int lr = tid >> 4;          // load row within pass
    int lc = tid & 15;          // load col (k)

    float acc[8][4];
    #pragma unroll
    for (int i = 0; i < 8; i++)
        #pragma unroll
        for (int j = 0; j < 4; j++) acc[i][j] = 0.f;

    for (int k0 = 0; k0 < K; k0 += 16) {
        #pragma unroll
        for (int p = 0; p < 8; p++) {
            int row = p * 16 + lr;
            float v = (bm + row < M) ? A[(size_t)(bm + row) * K + k0 + lc] : 0.f;
            As[lc][row] = v;
        }
        #pragma unroll
        for (int p = 0; p < 4; p++) {
            int r = p * 4 + (tid >> 6);
            Bs[r][tid & 63] = B[(size_t)(k0 + r) * N + bn + (tid & 63)];
        }
        __syncthreads();
        #pragma unroll
        for (int k = 0; k < 16; k++) {
            float4 a0 = *(const float4*)&As[k][ty * 8];
            float4 a1 = *(const float4*)&As[k][ty * 8 + 4];
            float4 b  = *(const float4*)&Bs[k][tx * 4];
            float av[8] = {a0.x, a0.y, a0.z, a0.w, a1.x, a1.y, a1.z, a1.w};
            float bv[4] = {b.x, b.y, b.z, b.w};
            #pragma unroll
            for (int i = 0; i < 8; i++)
                #pragma unroll
                for (int j = 0; j < 4; j++) acc[i][j] += av[i] * bv[j];
        }
        __syncthreads();
    }

    float4 bb = *(const float4*)(bias + bn + tx * 4);
    #pragma unroll
    for (int i = 0; i < 8; i++) {
        int row = bm + ty * 8 + i;
        if (row < M) {
            float4 v = make_float4(acc[i][0] + bb.x, acc[i][1] + bb.y,
                                   acc[i][2] + bb.z, acc[i][3] + bb.w);
            *(float4*)(C + (size_t)row * N + bn + tx * 4) = v;
        }
    }
}

// ---------------- layer-1 fused edge kernel: one warp per dst, online softmax ----------------
// lane l owns channels [8l, 8l+8); head = l/8; alpha reduction within 8-lane group.
__global__ __launch_bounds__(256) void edge1_kernel(const float* __restrict__ att,
                                                    const float* __restrict__ bias)
{
    int w = (blockIdx.x * 256 + threadIdx.x) >> 5;
    int lane = threadIdx.x & 31;
    if (w >= N2) return;
    int off = lane * 8;

    const float* xrp = g_xr1 + (size_t)w * D1 + off;
    float4 xrA = *(const float4*)xrp;
    float4 xrB = *(const float4*)(xrp + 4);
    float4 atA = *(const float4*)(att + off);
    float4 atB = *(const float4*)(att + off + 4);

    float m = -INFINITY, s = 0.f;
    float ac[8] = {0.f, 0.f, 0.f, 0.f, 0.f, 0.f, 0.f, 0.f};

    int jb = g_rp1[w], je = g_rp1[w + 1];
    for (int j = jb; j < je; ++j) {
        int src = g_csr1[j];
        const float* xp = g_xl1 + (size_t)src * D1 + off;
        float4 xA = *(const float4*)xp;
        float4 xB = *(const float4*)(xp + 4);
        float p =
            lrelu(xA.x + xrA.x) * atA.x + lrelu(xA.y + xrA.y) * atA.y +
            lrelu(xA.z + xrA.z) * atA.z + lrelu(xA.w + xrA.w) * atA.w +
            lrelu(xB.x + xrB.x) * atB.x + lrelu(xB.y + xrB.y) * atB.y +
            lrelu(xB.z + xrB.z) * atB.z + lrelu(xB.w + xrB.w) * atB.w;
        p += __shfl_xor_sync(FULLM, p, 1);
        p += __shfl_xor_sync(FULLM, p, 2);
        p += __shfl_xor_sync(FULLM, p, 4);
        float nm = fmaxf(m, p);
        float sc = __expf(m - nm);   // exp(-inf)=0 handles first edge
        float wg = __expf(p - nm);
        s = s * sc + wg;
        ac[0] = ac[0] * sc + wg * xA.x; ac[1] = ac[1] * sc + wg * xA.y;
        ac[2] = ac[2] * sc + wg * xA.z; ac[3] = ac[3] * sc + wg * xA.w;
        ac[4] = ac[4] * sc + wg * xB.x; ac[5] = ac[5] * sc + wg * xB.y;
        ac[6] = ac[6] * sc + wg * xB.z; ac[7] = ac[7] * sc + wg * xB.w;
        m = nm;
    }
    float inv = 1.f / (s + SM_EPS);
    float4 bA = *(const float4*)(bias + off);
    float4 bB = *(const float4*)(bias + off + 4);
    float4 o0 = make_float4(ac[0] * inv + bA.x, ac[1] * inv + bA.y,
                            ac[2] * inv + bA.z, ac[3] * inv + bA.w);
    float4 o1 = make_float4(ac[4] * inv + bB.x, ac[5] * inv + bB.y,
                            ac[6] * inv + bB.z, ac[7] * inv + bB.w);
    float* hp = g_h + (size_t)w * D1 + off;
    *(float4*)hp = o0;
    *(float4*)(hp + 4) = o1;
}

// ---------------- batchnorm (training-mode, biased var) ----------------
__global__ void bn_sum_kernel() {
    int col = threadIdx.x;   // 256 threads
    float s = 0.f;
    for (int r = blockIdx.x; r < N2; r += gridDim.x) s += g_h[(size_t)r * D1 + col];
    atomicAdd(&g_bn_sum[col], s);
}
__global__ void bn_var_kernel() {
    int col = threadIdx.x;
    float mu = g_bn_sum[col] * (1.f / N2);
    float s = 0.f;
    for (int r = blockIdx.x; r < N2; r += gridDim.x) {
        float d = g_h[(size_t)r * D1 + col] - mu;
        s += d * d;
    }
    atomicAdd(&g_bn_sqs[col], s);
}
__global__ void bn_final_kernel(const float* __restrict__ gamma, const float* __restrict__ beta) {
    int c = threadIdx.x;
    float mu = g_bn_sum[c] * (1.f / N2);
    float var = g_bn_sqs[c] * (1.f / N2);
    float sc = gamma[c] * rsqrtf(var + BN_EPS);
    g_bn_scale[c] = sc;
    g_bn_shift[c] = beta[c] - mu * sc;
}
__global__ void bn_apply_kernel() {
    int i = blockIdx.x * blockDim.x + threadIdx.x;
    if (i < N2 * D1) {
        int c = i & (D1 - 1);
        float v = g_h[i] * g_bn_scale[c] + g_bn_shift[c];
        g_h[i] = fmaxf(v, 0.f);
    }
}

// ---------------- layer-2 fused edge kernel + log_softmax ----------------
// one warp per dst; lane owns channels [2l, 2l+1]; single head spans whole warp.
__global__ __launch_bounds__(256) void edge2_kernel(const float* __restrict__ att,
                                                    const float* __restrict__ bias,
                                                    float* __restrict__ out)
{
    int w = (blockIdx.x * 256 + threadIdx.x) >> 5;
    int lane = threadIdx.x & 31;
    if (w >= N3) return;
    int off = lane * 2;

    float2 xr = *(const float2*)(g_xr2 + (size_t)w * D2 + off);
    float2 at = *(const float2*)(att + off);
    float m = -INFINITY, s = 0.f, a0 = 0.f, a1 = 0.f;

    int jb = g_rp2[w], je = g_rp2[w + 1];
    for (int j = jb; j < je; ++j) {
        int src = g_csr2[j];
        float2 xj = *(const float2*)(g_xl2 + (size_t)src * D2 + off);
        float p = lrelu(xj.x + xr.x) * at.x + lrelu(xj.y + xr.y) * at.y;
        #pragma unroll
        for (int o = 16; o > 0; o >>= 1) p += __shfl_xor_sync(FULLM, p, o);
        float nm = fmaxf(m, p);
        float sc = __expf(m - nm);
        float wg = __expf(p - nm);
        s = s * sc + wg;
        a0 = a0 * sc + wg * xj.x;
        a1 = a1 * sc + wg * xj.y;
        m = nm;
    }
    float inv = 1.f / (s + SM_EPS);
    float o0 = a0 * inv + bias[off];
    float o1 = a1 * inv + bias[off + 1];

    // fused row-wise log_softmax over 64 classes
    float mx = fmaxf(o0, o1);
    #pragma unroll
    for (int o = 16; o > 0; o >>= 1) mx = fmaxf(mx, __shfl_xor_sync(FULLM, mx, o));
    float se = __expf(o0 - mx) + __expf(o1 - mx);
    #pragma unroll
    for (int o = 16; o > 0; o >>= 1) se += __shfl_xor_sync(FULLM, se, o);
    float lse = __logf(se);
    float2 r = make_float2(o0 - mx - lse, o1 - mx - lse);
    *(float2*)(out + (size_t)w * D2 + off) = r;
}

// ---------------- launch ----------------
extern "C" void kernel_launch(void* const* d_in, const int* in_sizes, int n_in,
                              void* d_out, int out_size)
{
    const float* x       = (const float*)d_in[0];
    const int*   ei1_src = (const int*)d_in[1];
    const int*   ei1_dst = (const int*)d_in[2];
    const int*   ei2_src = (const int*)d_in[3];
    const int*   ei2_dst = (const int*)d_in[4];
    const float* W1l     = (const float*)d_in[5];
    const float* b1l     = (const float*)d_in[6];
    const float* W1r     = (const float*)d_in[7];
    const float* b1r     = (const float*)d_in[8];
    const float* att1    = (const float*)d_in[9];
    const float* bias1   = (const float*)d_in[10];
    const float* gamma   = (const float*)d_in[11];
    const float* beta    = (const float*)d_in[12];
    const float* W2l     = (const float*)d_in[13];
    const float* b2l     = (const float*)d_in[14];
    const float* W2r     = (const float*)d_in[15];
    const float* b2r     = (const float*)d_in[16];
    const float* att2    = (const float*)d_in[17];
    const float* bias2   = (const float*)d_in[18];
    float* out = (float*)d_out;

    float *p_xl1, *p_xr1, *p_h, *p_xl2, *p_xr2;
    cudaGetSymbolAddress((void**)&p_xl1, g_xl1);
    cudaGetSymbolAddress((void**)&p_xr1, g_xr1);
    cudaGetSymbolAddress((void**)&p_h,   g_h);
    cudaGetSymbolAddress((void**)&p_xl2, g_xl2);
    cudaGetSymbolAddress((void**)&p_xr2, g_xr2);

    // CSR build (independent of GEMMs)
    zero_kernel<<<(N2 + 255) / 256, 256>>>();
    hist_kernel<<<(E1 + 255) / 256, 256>>>(ei1_dst, ei2_dst);
    scan_kernel<<<1, 1024>>>(0);
    scan_kernel<<<1, 1024>>>(1);
    scatter_kernel<<<(E1 + 255) / 256, 256>>>(ei1_src, ei1_dst, E1, 0);
    scatter_kernel<<<(E2 + 255) / 256, 256>>>(ei2_src, ei2_dst, E2, 1);

    // layer 1 projections
    {
        dim3 g(D1 / 64, (N1 + 127) / 128);
        gemm_bias_kernel<<<g, 256>>>(x, W1l, b1l, p_xl1, N1, D1, 128);
    }
    {
        dim3 g(D1 / 64, (N2 + 127) / 128);
        gemm_bias_kernel<<<g, 256>>>(x, W1r, b1r, p_xr1, N2, D1, 128);
    }

    // layer 1 attention + aggregation
    edge1_kernel<<<(N2 * 32 + 255) / 256, 256>>>(att1, bias1);

    // batchnorm + relu (in place on g_h)
    bn_sum_kernel<<<256, 256>>>();
    bn_var_kernel<<<256, 256>>>();
    bn_final_kernel<<<1, 256>>>(gamma, beta);
    bn_apply_kernel<<<(N2 * D1 + 255) / 256, 256>>>();

    // layer 2 projections
    {
        dim3 g(D2 / 64, (N2 + 127) / 128);
        gemm_bias_kernel<<<g, 256>>>(p_h, W2l, b2l, p_xl2, N2, D2, D1);
    }
    {
        dim3 g(D2 / 64, (N3 + 127) / 128);
        gemm_bias_kernel<<<g, 256>>>(p_h, W2r, b2r, p_xr2, N3, D2, D1);
    }

    // layer 2 attention + aggregation + log_softmax
    edge2_kernel<<<(N3 * 32 + 255) / 256, 256>>>(att2, bias2, out);
}

// round 2
// speedup vs baseline: 1.3067x; 1.3067x over previous
#include <cuda_runtime.h>
#include <cuda_bf16.h>
#include <math.h>

// ---------------- problem constants ----------------
#define N1 160000
#define N2 40000
#define N3 10000
#define E1 800000
#define E2 200000
#define D1 256          // H1*HID
#define D2 64           // OUT
#define NEG_SLOPE 0.2f
#define BN_EPS 1e-5f
#define SM_EPS 1e-16f
#define FULLM 0xFFFFFFFFu

// ---------------- device scratch (allocation-free) ----------------
__device__ float g_xl1[(size_t)N1 * D1];   // 163.8 MB
__device__ float g_xr1[(size_t)N2 * D1];   // 41 MB
__device__ float g_h  [(size_t)N2 * D1];   // 41 MB   (layer1 out, BN+relu in place)
__device__ float g_xl2[(size_t)N2 * D2];   // 10.2 MB
__device__ float g_xr2[(size_t)N3 * D2];   // 2.6 MB

__device__ int g_cnt1[N2];
__device__ int g_rp1 [N2 + 1];
__device__ int g_cur1[N2];
__device__ int g_csr1[E1];

__device__ int g_cnt2[N3];
__device__ int g_rp2 [N3 + 1];
__device__ int g_cur2[N3];
__device__ int g_csr2[E2];

__device__ float g_bn_sum[D1];
__device__ float g_bn_sqs[D1];
__device__ float g_bn_scale[D1];
__device__ float g_bn_shift[D1];

__device__ __forceinline__ float lrelu(float v) { return v > 0.f ? v : NEG_SLOPE * v; }

// ---------------- CSR build ----------------
__global__ void zero_kernel() {
    int i = blockIdx.x * blockDim.x + threadIdx.x;
    if (i < N2) g_cnt1[i] = 0;
    if (i < N3) g_cnt2[i] = 0;
    if (i < D1) { g_bn_sum[i] = 0.f; g_bn_sqs[i] = 0.f; }
}

__global__ void hist_kernel(const int* __restrict__ d1, const int* __restrict__ d2) {
    int i = blockIdx.x * blockDim.x + threadIdx.x;
    if (i < E1) atomicAdd(&g_cnt1[d1[i]], 1);
    if (i < E2) atomicAdd(&g_cnt2[d2[i]], 1);
}

// 2-block warp-shuffle exclusive scan: blockIdx 0 -> layer1 (N2), 1 -> layer2 (N3)
__global__ __launch_bounds__(1024) void scan2_kernel() {
    int which = blockIdx.x;
    const int* cnt = which ? g_cnt2 : g_cnt1;
    int* rp  = which ? g_rp2  : g_rp1;
    int* cur = which ? g_cur2 : g_cur1;
    int n    = which ? N3     : N2;

    __shared__ int wsum[32];
    __shared__ int carry;
    int tid = threadIdx.x;
    int lane = tid & 31, wid = tid >> 5;
    if (tid == 0) carry = 0;
    __syncthreads();

    for (int base = 0; base < n; base += 4096) {
        int i0 = base + tid * 4;
        int v0 = (i0 + 0 < n) ? cnt[i0 + 0] : 0;
        int v1 = (i0 + 1 < n) ? cnt[i0 + 1] : 0;
        int v2 = (i0 + 2 < n) ? cnt[i0 + 2] : 0;
        int v3 = (i0 + 3 < n) ? cnt[i0 + 3] : 0;
        int tot = v0 + v1 + v2 + v3;
        // warp inclusive scan of tot
        int isum = tot;
        #pragma unroll
        for (int off = 1; off < 32; off <<= 1) {
            int t = __shfl_up_sync(FULLM, isum, off);
            if (lane >= off) isum += t;
        }
        if (lane == 31) wsum[wid] = isum;
        __syncthreads();
        if (wid == 0) {
            int s = wsum[lane];
            #pragma unroll
            for (int off = 1; off < 32; off <<= 1) {
                int t = __shfl_up_sync(FULLM, s, off);
                if (lane >= off) s += t;
            }
            wsum[lane] = s;
        }
        __syncthreads();
        int carryv = carry;
        int woff = (wid > 0) ? wsum[wid - 1] : 0;
        int excl = carryv + woff + (isum - tot);
        if (i0 + 0 < n) { rp[i0 + 0] = excl;                cur[i0 + 0] = excl; }
        if (i0 + 1 < n) { rp[i0 + 1] = excl + v0;           cur[i0 + 1] = excl + v0; }
        if (i0 + 2 < n) { rp[i0 + 2] = excl + v0 + v1;      cur[i0 + 2] = excl + v0 + v1; }
        if (i0 + 3 < n) { rp[i0 + 3] = excl + v0 + v1 + v2; cur[i0 + 3] = excl + v0 + v1 + v2; }
        __syncthreads();
        if (tid == 0) carry = carryv + wsum[31];
        __syncthreads();
    }
    if (tid == 0) rp[n] = carry;
}

__global__ void scatter_kernel(const int* __restrict__ src, const int* __restrict__ dst,
                               int E, int which) {
    int e = blockIdx.x * blockDim.x + threadIdx.x;
    if (e >= E) return;
    int d = dst[e];
    if (which) { int p = atomicAdd(&g_cur2[d], 1); g_csr2[p] = src[e]; }
    else       { int p = atomicAdd(&g_cur1[d], 1); g_csr1[p] = src[e]; }
}

// ---------------- tf32 tensor-core GEMM: C[M,N] = A[M,K] @ B[K,N] + bias[N] ----------------
// BM=128, BN=64, BK=32, 256 threads (8 warps: 4 in M x 2 in N), warp tile 32x32.
// Requires K % 32 == 0, N % 64 == 0.
__device__ __forceinline__ unsigned f2tf(float f) {
    unsigned r;
    asm("cvt.rna.tf32.f32 %0, %1;" : "=r"(r) : "f"(f));
    return r;
}
__device__ __forceinline__ void mma_tf32(float* d, const unsigned* a, const unsigned* b) {
    asm volatile("mma.sync.aligned.m16n8k8.row.col.f32.tf32.tf32.f32 "
        "{%0,%1,%2,%3}, {%4,%5,%6,%7}, {%8,%9}, {%0,%1,%2,%3};"
        : "+f"(d[0]), "+f"(d[1]), "+f"(d[2]), "+f"(d[3])
        : "r"(a[0]), "r"(a[1]), "r"(a[2]), "r"(a[3]), "r"(b[0]), "r"(b[1]));
}

__global__ __launch_bounds__(256) void gemm_tf32_kernel(
    const float* __restrict__ A, const float* __restrict__ B,
    const float* __restrict__ bias, float* __restrict__ C,
    int M, int N, int K)
{
    __shared__ float As[32][132];   // k-major; banks (4t+g) conflict-free on reads
    __shared__ float Bs[32][68];
    int tid = threadIdx.x;
    int lane = tid & 31, warp = tid >> 5;
    int wm = warp & 3, wn = warp >> 2;
    int g = lane >> 2, t = lane & 3;
    int bm = blockIdx.y * 128, bn = blockIdx.x * 64;

    float acc[2][4][4];
    #pragma unroll
    for (int mi = 0; mi < 2; mi++)
        #pragma unroll
        for (int ni = 0; ni < 4; ni++)
            #pragma unroll
            for (int j = 0; j < 4; j++) acc[mi][ni][j] = 0.f;

    for (int k0 = 0; k0 < K; k0 += 32) {
        // A tile 128x32 (transpose into k-major shared)
        #pragma unroll
        for (int i = 0; i < 4; i++) {
            int row = (tid >> 3) + i * 32;
            int col = (tid & 7) * 4;
            int gr = bm + row;
            float4 v = (gr < M) ? *(const float4*)(A + (size_t)gr * K + k0 + col)
                                : make_float4(0.f, 0.f, 0.f, 0.f);
            As[col + 0][row] = v.x; As[col + 1][row] = v.y;
            As[col + 2][row] = v.z; As[col + 3][row] = v.w;
        }
        // B tile 32x64 (no transpose)
        #pragma unroll
        for (int i = 0; i < 2; i++) {
            int idx = tid + i * 256;
            int row = idx >> 4;
            int col = (idx & 15) * 4;
            *(float4*)&Bs[row][col] = *(const float4*)(B + (size_t)(k0 + row) * N + bn + col);
        }
        __syncthreads();
        #pragma unroll
        for (int kk = 0; kk < 32; kk += 8) {
            unsigned af[2][4], bf[4][2];
            #pragma unroll
            for (int mi = 0; mi < 2; mi++) {
                int m0 = wm * 32 + mi * 16;
                af[mi][0] = f2tf(As[kk + t    ][m0 + g    ]);
                af[mi][1] = f2tf(As[kk + t    ][m0 + g + 8]);
                af[mi][2] = f2tf(As[kk + t + 4][m0 + g    ]);
                af[mi][3] = f2tf(As[kk + t + 4][m0 + g + 8]);
            }
            #pragma unroll
            for (int ni = 0; ni < 4; ni++) {
                int n0 = wn * 32 + ni * 8;
                bf[ni][0] = f2tf(Bs[kk + t    ][n0 + g]);
                bf[ni][1] = f2tf(Bs[kk + t + 4][n0 + g]);
            }
            #pragma unroll
            for (int mi = 0; mi < 2; mi++)
                #pragma unroll
                for (int ni = 0; ni < 4; ni++)
                    mma_tf32(acc[mi][ni], af[mi], bf[ni]);
        }
        __syncthreads();
    }

    #pragma unroll
    for (int mi = 0; mi < 2; mi++) {
        #pragma unroll
        for (int ni = 0; ni < 4; ni++) {
            int col = bn + wn * 32 + ni * 8 + 2 * t;
            float2 bb = *(const float2*)(bias + col);
            int r0 = bm + wm * 32 + mi * 16 + g;
            if (r0 < M) {
                float2 v = make_float2(acc[mi][ni][0] + bb.x, acc[mi][ni][1] + bb.y);
                *(float2*)(C + (size_t)r0 * N + col) = v;
            }
            int r1 = r0 + 8;
            if (r1 < M) {
                float2 v = make_float2(acc[mi][ni][2] + bb.x, acc[mi][ni][3] + bb.y);
                *(float2*)(C + (size_t)r1 * N + col) = v;
            }
        }
    }
}

// ---------------- layer-1 fused edge kernel: one warp per dst, online softmax ----------------
__global__ __launch_bounds__(256) void edge1_kernel(const float* __restrict__ att,
                                                    const float* __restrict__ bias)
{
    int w = (blockIdx.x * 256 + threadIdx.x) >> 5;
    int lane = threadIdx.x & 31;
    if (w >= N2) return;
    int off = lane * 8;

    const float* xrp = g_xr1 + (size_t)w * D1 + off;
    float4 xrA = *(const float4*)xrp;
    float4 xrB = *(const float4*)(xrp + 4);
    float4 atA = *(const float4*)(att + off);
    float4 atB = *(const float4*)(att + off + 4);

    float m = -INFINITY, s = 0.f;
    float ac[8] = {0.f, 0.f, 0.f, 0.f, 0.f, 0.f, 0.f, 0.f};

    int jb = g_rp1[w], je = g_rp1[w + 1];
    for (int j = jb; j < je; ++j) {
        int src = g_csr1[j];
        const float* xp = g_xl1 + (size_t)src * D1 + off;
        float4 xA = *(const float4*)xp;
        float4 xB = *(const float4*)(xp + 4);
        float p =
            lrelu(xA.x + xrA.x) * atA.x + lrelu(xA.y + xrA.y) * atA.y +
            lrelu(xA.z + xrA.z) * atA.z + lrelu(xA.w + xrA.w) * atA.w +
            lrelu(xB.x + xrB.x) * atB.x + lrelu(xB.y + xrB.y) * atB.y +
            lrelu(xB.z + xrB.z) * atB.z + lrelu(xB.w + xrB.w) * atB.w;
        p += __shfl_xor_sync(FULLM, p, 1);
        p += __shfl_xor_sync(FULLM, p, 2);
        p += __shfl_xor_sync(FULLM, p, 4);
        float nm = fmaxf(m, p);
        float sc = __expf(m - nm);
        float wg = __expf(p - nm);
        s = s * sc + wg;
        ac[0] = ac[0] * sc + wg * xA.x; ac[1] = ac[1] * sc + wg * xA.y;
        ac[2] = ac[2] * sc + wg * xA.z; ac[3] = ac[3] * sc + wg * xA.w;
        ac[4] = ac[4] * sc + wg * xB.x; ac[5] = ac[5] * sc + wg * xB.y;
        ac[6] = ac[6] * sc + wg * xB.z; ac[7] = ac[7] * sc + wg * xB.w;
        m = nm;
    }
    float inv = 1.f / (s + SM_EPS);
    float4 bA = *(const float4*)(bias + off);
    float4 bB = *(const float4*)(bias + off + 4);
    float4 o0 = make_float4(ac[0] * inv + bA.x, ac[1] * inv + bA.y,
                            ac[2] * inv + bA.z, ac[3] * inv + bA.w);
    float4 o1 = make_float4(ac[4] * inv + bB.x, ac[5] * inv + bB.y,
                            ac[6] * inv + bB.z, ac[7] * inv + bB.w);
    float* hp = g_h + (size_t)w * D1 + off;
    *(float4*)hp = o0;
    *(float4*)(hp + 4) = o1;
}

// ---------------- batchnorm (training-mode, biased var) ----------------
__global__ void bn_sum_kernel() {
    int col = threadIdx.x;
    float s = 0.f;
    for (int r = blockIdx.x; r < N2; r += gridDim.x) s += g_h[(size_t)r * D1 + col];
    atomicAdd(&g_bn_sum[col], s);
}
__global__ void bn_var_kernel() {
    int col = threadIdx.x;
    float mu = g_bn_sum[col] * (1.f / N2);
    float s = 0.f;
    for (int r = blockIdx.x; r < N2; r += gridDim.x) {
        float d = g_h[(size_t)r * D1 + col] - mu;
        s += d * d;
    }
    atomicAdd(&g_bn_sqs[col], s);
}
__global__ void bn_final_kernel(const float* __restrict__ gamma, const float* __restrict__ beta) {
    int c = threadIdx.x;
    float mu = g_bn_sum[c] * (1.f / N2);
    float var = g_bn_sqs[c] * (1.f / N2);
    float sc = gamma[c] * rsqrtf(var + BN_EPS);
    g_bn_scale[c] = sc;
    g_bn_shift[c] = beta[c] - mu * sc;
}
__global__ void bn_apply_kernel() {
    int i = blockIdx.x * blockDim.x + threadIdx.x;
    if (i < N2 * D1) {
        int c = i & (D1 - 1);
        float v = g_h[i] * g_bn_scale[c] + g_bn_shift[c];
        g_h[i] = fmaxf(v, 0.f);
    }
}

// ---------------- layer-2 fused edge kernel + log_softmax ----------------
__global__ __launch_bounds__(256) void edge2_kernel(const float* __restrict__ att,
                                                    const float* __restrict__ bias,
                                                    float* __restrict__ out)
{
    int w = (blockIdx.x * 256 + threadIdx.x) >> 5;
    int lane = threadIdx.x & 31;
    if (w >= N3) return;
    int off = lane * 2;

    float2 xr = *(const float2*)(g_xr2 + (size_t)w * D2 + off);
    float2 at = *(const float2*)(att + off);
    float m = -INFINITY, s = 0.f, a0 = 0.f, a1 = 0.f;

    int jb = g_rp2[w], je = g_rp2[w + 1];
    for (int j = jb; j < je; ++j) {
        int src = g_csr2[j];
        float2 xj = *(const float2*)(g_xl2 + (size_t)src * D2 + off);
        float p = lrelu(xj.x + xr.x) * at.x + lrelu(xj.y + xr.y) * at.y;
        #pragma unroll
        for (int o = 16; o > 0; o >>= 1) p += __shfl_xor_sync(FULLM, p, o);
        float nm = fmaxf(m, p);
        float sc = __expf(m - nm);
        float wg = __expf(p - nm);
        s = s * sc + wg;
        a0 = a0 * sc + wg * xj.x;
        a1 = a1 * sc + wg * xj.y;
        m = nm;
    }
    float inv = 1.f / (s + SM_EPS);
    float o0 = a0 * inv + bias[off];
    float o1 = a1 * inv + bias[off + 1];

    float mx = fmaxf(o0, o1);
    #pragma unroll
    for (int o = 16; o > 0; o >>= 1) mx = fmaxf(mx, __shfl_xor_sync(FULLM, mx, o));
    float se = __expf(o0 - mx) + __expf(o1 - mx);
    #pragma unroll
    for (int o = 16; o > 0; o >>= 1) se += __shfl_xor_sync(FULLM, se, o);
    float lse = __logf(se);
    float2 r = make_float2(o0 - mx - lse, o1 - mx - lse);
    *(float2*)(out + (size_t)w * D2 + off) = r;
}

// ---------------- launch ----------------
extern "C" void kernel_launch(void* const* d_in, const int* in_sizes, int n_in,
                              void* d_out, int out_size)
{
    const float* x       = (const float*)d_in[0];
    const int*   ei1_src = (const int*)d_in[1];
    const int*   ei1_dst = (const int*)d_in[2];
    const int*   ei2_src = (const int*)d_in[3];
    const int*   ei2_dst = (const int*)d_in[4];
    const float* W1l     = (const float*)d_in[5];
    const float* b1l     = (const float*)d_in[6];
    const float* W1r     = (const float*)d_in[7];
    const float* b1r     = (const float*)d_in[8];
    const float* att1    = (const float*)d_in[9];
    const float* bias1   = (const float*)d_in[10];
    const float* gamma   = (const float*)d_in[11];
    const float* beta    = (const float*)d_in[12];
    const float* W2l     = (const float*)d_in[13];
    const float* b2l     = (const float*)d_in[14];
    const float* W2r     = (const float*)d_in[15];
    const float* b2r     = (const float*)d_in[16];
    const float* att2    = (const float*)d_in[17];
    const float* bias2   = (const float*)d_in[18];
    float* out = (float*)d_out;

    float *p_xl1, *p_xr1, *p_h, *p_xl2, *p_xr2;
    cudaGetSymbolAddress((void**)&p_xl1, g_xl1);
    cudaGetSymbolAddress((void**)&p_xr1, g_xr1);
    cudaGetSymbolAddress((void**)&p_h,   g_h);
    cudaGetSymbolAddress((void**)&p_xl2, g_xl2);
    cudaGetSymbolAddress((void**)&p_xr2, g_xr2);

    // CSR build
    zero_kernel<<<(N2 + 255) / 256, 256>>>();
    hist_kernel<<<(E1 + 255) / 256, 256>>>(ei1_dst, ei2_dst);
    scan2_kernel<<<2, 1024>>>();
    scatter_kernel<<<(E1 + 255) / 256, 256>>>(ei1_src, ei1_dst, E1, 0);
    scatter_kernel<<<(E2 + 255) / 256, 256>>>(ei2_src, ei2_dst, E2, 1);

    // layer 1 projections (tf32 tensor cores)
    {
        dim3 g(D1 / 64, (N1 + 127) / 128);
        gemm_tf32_kernel<<<g, 256>>>(x, W1l, b1l, p_xl1, N1, D1, 128);
    }
    {
        dim3 g(D1 / 64, (N2 + 127) / 128);
        gemm_tf32_kernel<<<g, 256>>>(x, W1r, b1r, p_xr1, N2, D1, 128);
    }

    // layer 1 attention + aggregation
    edge1_kernel<<<(N2 * 32 + 255) / 256, 256>>>(att1, bias1);

    // batchnorm + relu (in place on g_h)
    bn_sum_kernel<<<256, 256>>>();
    bn_var_kernel<<<256, 256>>>();
    bn_final_kernel<<<1, 256>>>(gamma, beta);
    bn_apply_kernel<<<(N2 * D1 + 255) / 256, 256>>>();

    // layer 2 projections (tf32 tensor cores)
    {
        dim3 g(D2 / 64, (N2 + 127) / 128);
        gemm_tf32_kernel<<<g, 256>>>(p_h, W2l, b2l, p_xl2, N2, D2, D1);
    }
    {
        dim3 g(D2 / 64, (N3 + 127) / 128);
        gemm_tf32_kernel<<<g, 256>>>(p_h, W2r, b2r, p_xr2, N3, D2, D1);
    }

    // layer 2 attention + aggregation + log_softmax
    edge2_kernel<<<(N3 * 32 + 255) / 256, 256>>>(att2, bias2, out);
}

// round 4
// speedup vs baseline: 1.6266x; 1.2447x over previous
#include <cuda_runtime.h>
#include <cuda_bf16.h>
#include <cuda_fp16.h>
#include <math.h>

// ---------------- problem constants ----------------
#define N1 160000
#define N2 40000
#define N3 10000
#define E1 800000
#define E2 200000
#define D1 256          // H1*HID
#define D2 64           // OUT
#define NEG_SLOPE 0.2f
#define BN_EPS 1e-5f
#define SM_EPS 1e-16f
#define FULLM 0xFFFFFFFFu

// ---------------- device scratch (allocation-free) ----------------
__device__ __half g_xl1h[(size_t)N1 * D1];   // 82 MB  (fp16 gather table)
__device__ float  g_xr1[(size_t)N2 * D1];    // 41 MB
__device__ float  g_h  [(size_t)N2 * D1];    // 41 MB  (layer1 out, pre-BN)
__device__ float  g_xl2[(size_t)N2 * D2];    // 10.2 MB
__device__ float  g_xr2[(size_t)N3 * D2];    // 2.6 MB

__device__ int g_cnt1[N2];
__device__ int g_rp1 [N2 + 1];
__device__ int g_cur1[N2];
__device__ int g_csr1[E1];

__device__ int g_cnt2[N3];
__device__ int g_rp2 [N3 + 1];
__device__ int g_cur2[N3];
__device__ int g_csr2[E2];

__device__ float g_bn_sum[D1];
__device__ float g_bn_sqs[D1];
__device__ float g_bn_scale[D1];
__device__ float g_bn_shift[D1];

__device__ __forceinline__ float lrelu(float v) { return v > 0.f ? v : NEG_SLOPE * v; }

// ---------------- CSR build ----------------
__global__ void zero_kernel() {
    int i = blockIdx.x * blockDim.x + threadIdx.x;
    if (i < N2) g_cnt1[i] = 0;
    if (i < N3) g_cnt2[i] = 0;
    if (i < D1) { g_bn_sum[i] = 0.f; g_bn_sqs[i] = 0.f; }
}

__global__ void hist_kernel(const int* __restrict__ d1, const int* __restrict__ d2) {
    int i = blockIdx.x * blockDim.x + threadIdx.x;
    if (i < E1) atomicAdd(&g_cnt1[d1[i]], 1);
    if (i < E2) atomicAdd(&g_cnt2[d2[i]], 1);
}

// 2-block warp-shuffle exclusive scan: blockIdx 0 -> layer1 (N2), 1 -> layer2 (N3)
__global__ __launch_bounds__(1024) void scan2_kernel() {
    int which = blockIdx.x;
    const int* cnt = which ? g_cnt2 : g_cnt1;
    int* rp  = which ? g_rp2  : g_rp1;
    int* cur = which ? g_cur2 : g_cur1;
    int n    = which ? N3     : N2;

    __shared__ int wsum[32];
    __shared__ int carry;
    int tid = threadIdx.x;
    int lane = tid & 31, wid = tid >> 5;
    if (tid == 0) carry = 0;
    __syncthreads();

    for (int base = 0; base < n; base += 4096) {
        int i0 = base + tid * 4;
        int v0 = (i0 + 0 < n) ? cnt[i0 + 0] : 0;
        int v1 = (i0 + 1 < n) ? cnt[i0 + 1] : 0;
        int v2 = (i0 + 2 < n) ? cnt[i0 + 2] : 0;
        int v3 = (i0 + 3 < n) ? cnt[i0 + 3] : 0;
        int tot = v0 + v1 + v2 + v3;
        int isum = tot;
        #pragma unroll
        for (int off = 1; off < 32; off <<= 1) {
            int t = __shfl_up_sync(FULLM, isum, off);
            if (lane >= off) isum += t;
        }
        if (lane == 31) wsum[wid] = isum;
        __syncthreads();
        if (wid == 0) {
            int s = wsum[lane];
            #pragma unroll
            for (int off = 1; off < 32; off <<= 1) {
                int t = __shfl_up_sync(FULLM, s, off);
                if (lane >= off) s += t;
            }
            wsum[lane] = s;
        }
        __syncthreads();
        int carryv = carry;
        int woff = (wid > 0) ? wsum[wid - 1] : 0;
        int excl = carryv + woff + (isum - tot);
        if (i0 + 0 < n) { rp[i0 + 0] = excl;                cur[i0 + 0] = excl; }
        if (i0 + 1 < n) { rp[i0 + 1] = excl + v0;           cur[i0 + 1] = excl + v0; }
        if (i0 + 2 < n) { rp[i0 + 2] = excl + v0 + v1;      cur[i0 + 2] = excl + v0 + v1; }
        if (i0 + 3 < n) { rp[i0 + 3] = excl + v0 + v1 + v2; cur[i0 + 3] = excl + v0 + v1 + v2; }
        __syncthreads();
        if (tid == 0) carry = carryv + wsum[31];
        __syncthreads();
    }
    if (tid == 0) rp[n] = carry;
}

__global__ void scatter_kernel(const int* __restrict__ src, const int* __restrict__ dst,
                               int E, int which) {
    int e = blockIdx.x * blockDim.x + threadIdx.x;
    if (e >= E) return;
    int d = dst[e];
    if (which) { int p = atomicAdd(&g_cur2[d], 1); g_csr2[p] = src[e]; }
    else       { int p = atomicAdd(&g_cur1[d], 1); g_csr1[p] = src[e]; }
}

// ---------------- tf32 mma helpers ----------------
__device__ __forceinline__ unsigned f2tf(float f) {
    unsigned r;
    asm("cvt.rna.tf32.f32 %0, %1;" : "=r"(r) : "f"(f));
    return r;
}
__device__ __forceinline__ void mma_tf32(float* d, const unsigned* a, const unsigned* b) {
    asm volatile("mma.sync.aligned.m16n8k8.row.col.f32.tf32.tf32.f32 "
        "{%0,%1,%2,%3}, {%4,%5,%6,%7}, {%8,%9}, {%0,%1,%2,%3};"
        : "+f"(d[0]), "+f"(d[1]), "+f"(d[2]), "+f"(d[3])
        : "r"(a[0]), "r"(a[1]), "r"(a[2]), "r"(a[3]), "r"(b[0]), "r"(b[1]));
}

// ---------------- GEMM1: C_fp16[M,256] = A[M,128] @ B[128,256] + bias ----------------
// BM=64, BN=256 (full row -> A read exactly once), BK=32, 256 threads (2x4 warps).
__global__ __launch_bounds__(256) void gemm1_kernel(
    const float* __restrict__ A, const float* __restrict__ B,
    const float* __restrict__ bias, __half* __restrict__ C, int M)
{
    __shared__ float As[32][68];
    __shared__ float Bs[32][260];
    const int K = 128;
    int tid = threadIdx.x;
    int lane = tid & 31, warp = tid >> 5;
    int wm = warp & 1, wn = warp >> 1;       // 2 x 4 warps
    int g = lane >> 2, t = lane & 3;
    int bm = blockIdx.x * 64;

    float acc[2][8][4];
    #pragma unroll
    for (int mi = 0; mi < 2; mi++)
        #pragma unroll
        for (int ni = 0; ni < 8; ni++)
            #pragma unroll
            for (int j = 0; j < 4; j++) acc[mi][ni][j] = 0.f;

    for (int k0 = 0; k0 < K; k0 += 32) {
        // A tile 64x32, transposed into k-major shared
        #pragma unroll
        for (int i = 0; i < 2; i++) {
            int row = (tid >> 3) + i * 32;
            int col = (tid & 7) * 4;
            float4 v = *(const float4*)(A + (size_t)(bm + row) * K + k0 + col);
            As[col + 0][row] = v.x; As[col + 1][row] = v.y;
            As[col + 2][row] = v.z; As[col + 3][row] = v.w;
        }
        // B tile 32x256
        #pragma unroll
        for (int p = 0; p < 8; p++) {
            int idx = tid + p * 256;
            int row = idx >> 6;
            int col = (idx & 63) * 4;
            *(float4*)&Bs[row][col] = *(const float4*)(B + (size_t)(k0 + row) * 256 + col);
        }
        __syncthreads();
        #pragma unroll
        for (int kk = 0; kk < 32; kk += 8) {
            unsigned af[2][4], bf[8][2];
            #pragma unroll
            for (int mi = 0; mi < 2; mi++) {
                int m0 = wm * 32 + mi * 16;
                af[mi][0] = f2tf(As[kk + t    ][m0 + g    ]);
                af[mi][1] = f2tf(As[kk + t    ][m0 + g + 8]);
                af[mi][2] = f2tf(As[kk + t + 4][m0 + g    ]);
                af[mi][3] = f2tf(As[kk + t + 4][m0 + g + 8]);
            }
            #pragma unroll
            for (int ni = 0; ni < 8; ni++) {
                int n0 = wn * 64 + ni * 8;
                bf[ni][0] = f2tf(Bs[kk + t    ][n0 + g]);
                bf[ni][1] = f2tf(Bs[kk + t + 4][n0 + g]);
            }
            #pragma unroll
            for (int mi = 0; mi < 2; mi++)
                #pragma unroll
                for (int ni = 0; ni < 8; ni++)
                    mma_tf32(acc[mi][ni], af[mi], bf[ni]);
        }
        __syncthreads();
    }

    #pragma unroll
    for (int mi = 0; mi < 2; mi++) {
        #pragma unroll
        for (int ni = 0; ni < 8; ni++) {
            int col = wn * 64 + ni * 8 + 2 * t;
            float2 bb = *(const float2*)(bias + col);
            int r0 = bm + wm * 32 + mi * 16 + g;
            *(__half2*)(C + (size_t)r0 * 256 + col) =
                __floats2half2_rn(acc[mi][ni][0] + bb.x, acc[mi][ni][1] + bb.y);
            *(__half2*)(C + (size_t)(r0 + 8) * 256 + col) =
                __floats2half2_rn(acc[mi][ni][2] + bb.x, acc[mi][ni][3] + bb.y);
        }
    }
}

// ---------------- general tf32 GEMM (fp32 out), optional fused BN+ReLU on A ----------------
// BM=128, BN=64, BK=32, 256 threads (4x2 warps). K%32==0, N%64==0.
__global__ __launch_bounds__(256) void gemm_tf32_kernel(
    const float* __restrict__ A, const float* __restrict__ B,
    const float* __restrict__ bias, float* __restrict__ C,
    int M, int N, int K, int apply_bn)
{
    __shared__ float As[32][132];
    __shared__ float Bs[32][68];
    int tid = threadIdx.x;
    int lane = tid & 31, warp = tid >> 5;
    int wm = warp & 3, wn = warp >> 2;
    int g = lane >> 2, t = lane & 3;
    int bm = blockIdx.y * 128, bn = blockIdx.x * 64;

    float acc[2][4][4];
    #pragma unroll
    for (int mi = 0; mi < 2; mi++)
        #pragma unroll
        for (int ni = 0; ni < 4; ni++)
            #pragma unroll
            for (int j = 0; j < 4; j++) acc[mi][ni][j] = 0.f;

    for (int k0 = 0; k0 < K; k0 += 32) {
        #pragma unroll
        for (int i = 0; i < 4; i++) {
            int row = (tid >> 3) + i * 32;
            int col = (tid & 7) * 4;
            int gr = bm + row;
            float4 v = (gr < M) ? *(const float4*)(A + (size_t)gr * K + k0 + col)
                                : make_float4(0.f, 0.f, 0.f, 0.f);
            if (apply_bn) {
                float4 sc = *(const float4*)(g_bn_scale + k0 + col);
                float4 sh = *(const float4*)(g_bn_shift + k0 + col);
                v.x = fmaxf(v.x * sc.x + sh.x, 0.f);
                v.y = fmaxf(v.y * sc.y + sh.y, 0.f);
                v.z = fmaxf(v.z * sc.z + sh.z, 0.f);
                v.w = fmaxf(v.w * sc.w + sh.w, 0.f);
            }
            As[col + 0][row] = v.x; As[col + 1][row] = v.y;
            As[col + 2][row] = v.z; As[col + 3][row] = v.w;
        }
        #pragma unroll
        for (int i = 0; i < 2; i++) {
            int idx = tid + i * 256;
            int row = idx >> 4;
            int col = (idx & 15) * 4;
            *(float4*)&Bs[row][col] = *(const float4*)(B + (size_t)(k0 + row) * N + bn + col);
        }
        __syncthreads();
        #pragma unroll
        for (int kk = 0; kk < 32; kk += 8) {
            unsigned af[2][4], bf[4][2];
            #pragma unroll
            for (int mi = 0; mi < 2; mi++) {
                int m0 = wm * 32 + mi * 16;
                af[mi][0] = f2tf(As[kk + t    ][m0 + g    ]);
                af[mi][1] = f2tf(As[kk + t    ][m0 + g + 8]);
                af[mi][2] = f2tf(As[kk + t + 4][m0 + g    ]);
                af[mi][3] = f2tf(As[kk + t + 4][m0 + g + 8]);
            }
            #pragma unroll
            for (int ni = 0; ni < 4; ni++) {
                int n0 = wn * 32 + ni * 8;
                bf[ni][0] = f2tf(Bs[kk + t    ][n0 + g]);
                bf[ni][1] = f2tf(Bs[kk + t + 4][n0 + g]);
            }
            #pragma unroll
            for (int mi = 0; mi < 2; mi++)
                #pragma unroll
                for (int ni = 0; ni < 4; ni++)
                    mma_tf32(acc[mi][ni], af[mi], bf[ni]);
        }
        __syncthreads();
    }

    #pragma unroll
    for (int mi = 0; mi < 2; mi++) {
        #pragma unroll
        for (int ni = 0; ni < 4; ni++) {
            int col = bn + wn * 32 + ni * 8 + 2 * t;
            float2 bb = *(const float2*)(bias + col);
            int r0 = bm + wm * 32 + mi * 16 + g;
            if (r0 < M) {
                float2 v = make_float2(acc[mi][ni][0] + bb.x, acc[mi][ni][1] + bb.y);
                *(float2*)(C + (size_t)r0 * N + col) = v;
            }
            int r1 = r0 + 8;
            if (r1 < M) {
                float2 v = make_float2(acc[mi][ni][2] + bb.x, acc[mi][ni][3] + bb.y);
                *(float2*)(C + (size_t)r1 * N + col) = v;
            }
        }
    }
}

// ---------------- layer-1 fused edge kernel (fp16 gather table) ----------------
__global__ __launch_bounds__(256) void edge1_kernel(const float* __restrict__ att,
                                                    const float* __restrict__ bias)
{
    int w = (blockIdx.x * 256 + threadIdx.x) >> 5;
    int lane = threadIdx.x & 31;
    if (w >= N2) return;
    int off = lane * 8;

    const float* xrp = g_xr1 + (size_t)w * D1 + off;
    float4 xrA = *(const float4*)xrp;
    float4 xrB = *(const float4*)(xrp + 4);
    float4 atA = *(const float4*)(att + off);
    float4 atB = *(const float4*)(att + off + 4);

    float m = -INFINITY, s = 0.f;
    float ac[8] = {0.f, 0.f, 0.f, 0.f, 0.f, 0.f, 0.f, 0.f};

    int jb = g_rp1[w], je = g_rp1[w + 1];
    for (int j = jb; j < je; ++j) {
        int src = g_csr1[j];
        uint4 raw = *(const uint4*)(g_xl1h + (size_t)src * D1 + off);
        float2 f0 = __half22float2(*reinterpret_cast<const __half2*>(&raw.x));
        float2 f1 = __half22float2(*reinterpret_cast<const __half2*>(&raw.y));
        float2 f2 = __half22float2(*reinterpret_cast<const __half2*>(&raw.z));
        float2 f3 = __half22float2(*reinterpret_cast<const __half2*>(&raw.w));
        float p =
            lrelu(f0.x + xrA.x) * atA.x + lrelu(f0.y + xrA.y) * atA.y +
            lrelu(f1.x + xrA.z) * atA.z + lrelu(f1.y + xrA.w) * atA.w +
            lrelu(f2.x + xrB.x) * atB.x + lrelu(f2.y + xrB.y) * atB.y +
            lrelu(f3.x + xrB.z) * atB.z + lrelu(f3.y + xrB.w) * atB.w;
        p += __shfl_xor_sync(FULLM, p, 1);
        p += __shfl_xor_sync(FULLM, p, 2);
        p += __shfl_xor_sync(FULLM, p, 4);
        float nm = fmaxf(m, p);
        float sc = __expf(m - nm);
        float wg = __expf(p - nm);
        s = s * sc + wg;
        ac[0] = ac[0] * sc + wg * f0.x; ac[1] = ac[1] * sc + wg * f0.y;
        ac[2] = ac[2] * sc + wg * f1.x; ac[3] = ac[3] * sc + wg * f1.y;
        ac[4] = ac[4] * sc + wg * f2.x; ac[5] = ac[5] * sc + wg * f2.y;
        ac[6] = ac[6] * sc + wg * f3.x; ac[7] = ac[7] * sc + wg * f3.y;
        m = nm;
    }
    float inv = 1.f / (s + SM_EPS);
    float4 bA = *(const float4*)(bias + off);
    float4 bB = *(const float4*)(bias + off + 4);
    float4 o0 = make_float4(ac[0] * inv + bA.x, ac[1] * inv + bA.y,
                            ac[2] * inv + bA.z, ac[3] * inv + bA.w);
    float4 o1 = make_float4(ac[4] * inv + bB.x, ac[5] * inv + bB.y,
                            ac[6] * inv + bB.z, ac[7] * inv + bB.w);
    float* hp = g_h + (size_t)w * D1 + off;
    *(float4*)hp = o0;
    *(float4*)(hp + 4) = o1;
}

// ---------------- batchnorm statistics (single pass) ----------------
__global__ void bn_stats_kernel() {
    int col = threadIdx.x;   // 256 threads
    float s = 0.f, q = 0.f;
    for (int r = blockIdx.x; r < N2; r += gridDim.x) {
        float v = g_h[(size_t)r * D1 + col];
        s += v;
        q += v * v;
    }
    atomicAdd(&g_bn_sum[col], s);
    atomicAdd(&g_bn_sqs[col], q);
}
__global__ void bn_final_kernel(const float* __restrict__ gamma, const float* __restrict__ beta) {
    int c = threadIdx.x;
    float mu = g_bn_sum[c] * (1.f / N2);
    float var = g_bn_sqs[c] * (1.f / N2) - mu * mu;
    var = fmaxf(var, 0.f);
    float sc = gamma[c] * rsqrtf(var + BN_EPS);
    g_bn_scale[c] = sc;
    g_bn_shift[c] = beta[c] - mu * sc;
}

// ---------------- layer-2 fused edge kernel + log_softmax ----------------
__global__ __launch_bounds__(256) void edge2_kernel(const float* __restrict__ att,
                                                    const float* __restrict__ bias,
                                                    float* __restrict__ out)
{
    int w = (blockIdx.x * 256 + threadIdx.x) >> 5;
    int lane = threadIdx.x & 31;
    if (w >= N3) return;
    int off = lane * 2;

    float2 xr = *(const float2*)(g_xr2 + (size_t)w * D2 + off);
    float2 at = *(const float2*)(att + off);
    float m = -INFINITY, s = 0.f, a0 = 0.f, a1 = 0.f;

    int jb = g_rp2[w], je = g_rp2[w + 1];
    for (int j = jb; j < je; ++j) {
        int src = g_csr2[j];
        float2 xj = *(const float2*)(g_xl2 + (size_t)src * D2 + off);
        float p = lrelu(xj.x + xr.x) * at.x + lrelu(xj.y + xr.y) * at.y;
        #pragma unroll
        for (int o = 16; o > 0; o >>= 1) p += __shfl_xor_sync(FULLM, p, o);
        float nm = fmaxf(m, p);
        float sc = __expf(m - nm);
        float wg = __expf(p - nm);
        s = s * sc + wg;
        a0 = a0 * sc + wg * xj.x;
        a1 = a1 * sc + wg * xj.y;
        m = nm;
    }
    float inv = 1.f / (s + SM_EPS);
    float o0 = a0 * inv + bias[off];
    float o1 = a1 * inv + bias[off + 1];

    float mx = fmaxf(o0, o1);
    #pragma unroll
    for (int o = 16; o > 0; o >>= 1) mx = fmaxf(mx, __shfl_xor_sync(FULLM, mx, o));
    float se = __expf(o0 - mx) + __expf(o1 - mx);
    #pragma unroll
    for (int o = 16; o > 0; o >>= 1) se += __shfl_xor_sync(FULLM, se, o);
    float lse = __logf(se);
    float2 r = make_float2(o0 - mx - lse, o1 - mx - lse);
    *(float2*)(out + (size_t)w * D2 + off) = r;
}

// ---------------- launch ----------------
extern "C" void kernel_launch(void* const* d_in, const int* in_sizes, int n_in,
                              void* d_out, int out_size)
{
    const float* x       = (const float*)d_in[0];
    const int*   ei1_src = (const int*)d_in[1];
    const int*   ei1_dst = (const int*)d_in[2];
    const int*   ei2_src = (const int*)d_in[3];
    const int*   ei2_dst = (const int*)d_in[4];
    const float* W1l     = (const float*)d_in[5];
    const float* b1l     = (const float*)d_in[6];
    const float* W1r     = (const float*)d_in[7];
    const float* b1r     = (const float*)d_in[8];
    const float* att1    = (const float*)d_in[9];
    const float* bias1   = (const float*)d_in[10];
    const float* gamma   = (const float*)d_in[11];
    const float* beta    = (const float*)d_in[12];
    const float* W2l     = (const float*)d_in[13];
    const float* b2l     = (const float*)d_in[14];
    const float* W2r     = (const float*)d_in[15];
    const float* b2r     = (const float*)d_in[16];
    const float* att2    = (const float*)d_in[17];
    const float* bias2   = (const float*)d_in[18];
    float* out = (float*)d_out;

    __half* p_xl1h;
    float *p_xr1, *p_h, *p_xl2, *p_xr2;
    cudaGetSymbolAddress((void**)&p_xl1h, g_xl1h);
    cudaGetSymbolAddress((void**)&p_xr1, g_xr1);
    cudaGetSymbolAddress((void**)&p_h,   g_h);
    cudaGetSymbolAddress((void**)&p_xl2, g_xl2);
    cudaGetSymbolAddress((void**)&p_xr2, g_xr2);

    // CSR build
    zero_kernel<<<(N2 + 255) / 256, 256>>>();
    hist_kernel<<<(E1 + 255) / 256, 256>>>(ei1_dst, ei2_dst);
    scan2_kernel<<<2, 1024>>>();
    scatter_kernel<<<(E1 + 255) / 256, 256>>>(ei1_src, ei1_dst, E1, 0);
    scatter_kernel<<<(E2 + 255) / 256, 256>>>(ei2_src, ei2_dst, E2, 1);

    // layer 1 projections
    gemm1_kernel<<<N1 / 64, 256>>>(x, W1l, b1l, p_xl1h, N1);        // fp16 out, A read once
    {
        dim3 g(D1 / 64, (N2 + 127) / 128);
        gemm_tf32_kernel<<<g, 256>>>(x, W1r, b1r, p_xr1, N2, D1, 128, 0);
    }

    // layer 1 attention + aggregation
    edge1_kernel<<<(N2 * 32 + 255) / 256, 256>>>(att1, bias1);

    // batchnorm stats (apply is fused into layer-2 GEMM A loads)
    bn_stats_kernel<<<256, 256>>>();
    bn_final_kernel<<<1, 256>>>(gamma, beta);

    // layer 2 projections (BN+ReLU fused into A load)
    {
        dim3 g(D2 / 64, (N2 + 127) / 128);
        gemm_tf32_kernel<<<g, 256>>>(p_h, W2l, b2l, p_xl2, N2, D2, D1, 1);
    }
    {
        dim3 g(D2 / 64, (N3 + 127) / 128);
        gemm_tf32_kernel<<<g, 256>>>(p_h, W2r, b2r, p_xr2, N3, D2, D1, 1);
    }

    // layer 2 attention + aggregation + log_softmax
    edge2_kernel<<<(N3 * 32 + 255) / 256, 256>>>(att2, bias2, out);
}

// round 6
// speedup vs baseline: 1.8018x; 1.1077x over previous
#include <cuda_runtime.h>
#include <cuda_bf16.h>
#include <cuda_fp16.h>
#include <math.h>

// ---------------- problem constants ----------------
#define N1 160000
#define N2 40000
#define N3 10000
#define E1 800000
#define E2 200000
#define D1 256          // H1*HID
#define D2 64           // OUT
#define NEG_SLOPE 0.2f
#define BN_EPS 1e-5f
#define SM_EPS 1e-16f
#define FULLM 0xFFFFFFFFu

// ---------------- device scratch (allocation-free) ----------------
__device__ __half g_xh  [(size_t)N1 * 128];  // 41 MB  fp16 copy of x
__device__ __half g_xl1h[(size_t)N1 * D1];   // 82 MB  fp16 gather table
__device__ float  g_xr1[(size_t)N2 * D1];    // 41 MB
__device__ float  g_h  [(size_t)N2 * D1];    // 41 MB  (layer1 out, pre-BN)
__device__ float  g_xl2[(size_t)N2 * D2];    // 10.2 MB
__device__ float  g_xr2[(size_t)N3 * D2];    // 2.6 MB

__device__ __half g_w1lt[D1 * 128];          // [N=256][K=128]
__device__ __half g_w1rt[D1 * 128];
__device__ __half g_w2lt[D2 * D1];           // [N=64][K=256]
__device__ __half g_w2rt[D2 * D1];

__device__ int g_cnt1[N2];
__device__ int g_rp1 [N2 + 1];
__device__ int g_cur1[N2];
__device__ int g_csr1[E1];

__device__ int g_cnt2[N3];
__device__ int g_rp2 [N3 + 1];
__device__ int g_cur2[N3];
__device__ int g_csr2[E2];

__device__ float g_bn_sum[D1];
__device__ float g_bn_sqs[D1];
__device__ float g_bn_scale[D1];
__device__ float g_bn_shift[D1];

__device__ __forceinline__ float lrelu(float v) { return v > 0.f ? v : NEG_SLOPE * v; }

// ---------------- CSR build ----------------
__global__ void zero_kernel() {
    int i = blockIdx.x * blockDim.x + threadIdx.x;
    if (i < N2) g_cnt1[i] = 0;
    if (i < N3) g_cnt2[i] = 0;
    if (i < D1) { g_bn_sum[i] = 0.f; g_bn_sqs[i] = 0.f; }
}

__global__ void hist_kernel(const int* __restrict__ d1, const int* __restrict__ d2) {
    int i = blockIdx.x * blockDim.x + threadIdx.x;
    if (i < E1) atomicAdd(&g_cnt1[d1[i]], 1);
    if (i < E2) atomicAdd(&g_cnt2[d2[i]], 1);
}

// 2-block warp-shuffle exclusive scan: blockIdx 0 -> layer1 (N2), 1 -> layer2 (N3)
__global__ __launch_bounds__(1024) void scan2_kernel() {
    int which = blockIdx.x;
    const int* cnt = which ? g_cnt2 : g_cnt1;
    int* rp  = which ? g_rp2  : g_rp1;
    int* cur = which ? g_cur2 : g_cur1;
    int n    = which ? N3     : N2;

    __shared__ int wsum[32];
    __shared__ int carry;
    int tid = threadIdx.x;
    int lane = tid & 31, wid = tid >> 5;
    if (tid == 0) carry = 0;
    __syncthreads();

    for (int base = 0; base < n; base += 4096) {
        int i0 = base + tid * 4;
        int v0 = (i0 + 0 < n) ? cnt[i0 + 0] : 0;
        int v1 = (i0 + 1 < n) ? cnt[i0 + 1] : 0;
        int v2 = (i0 + 2 < n) ? cnt[i0 + 2] : 0;
        int v3 = (i0 + 3 < n) ? cnt[i0 + 3] : 0;
        int tot = v0 + v1 + v2 + v3;
        int isum = tot;
        #pragma unroll
        for (int off = 1; off < 32; off <<= 1) {
            int t = __shfl_up_sync(FULLM, isum, off);
            if (lane >= off) isum += t;
        }
        if (lane == 31) wsum[wid] = isum;
        __syncthreads();
        if (wid == 0) {
            int s = wsum[lane];
            #pragma unroll
            for (int off = 1; off < 32; off <<= 1) {
                int t = __shfl_up_sync(FULLM, s, off);
                if (lane >= off) s += t;
            }
            wsum[lane] = s;
        }
        __syncthreads();
        int carryv = carry;
        int woff = (wid > 0) ? wsum[wid - 1] : 0;
        int excl = carryv + woff + (isum - tot);
        if (i0 + 0 < n) { rp[i0 + 0] = excl;                cur[i0 + 0] = excl; }
        if (i0 + 1 < n) { rp[i0 + 1] = excl + v0;           cur[i0 + 1] = excl + v0; }
        if (i0 + 2 < n) { rp[i0 + 2] = excl + v0 + v1;      cur[i0 + 2] = excl + v0 + v1; }
        if (i0 + 3 < n) { rp[i0 + 3] = excl + v0 + v1 + v2; cur[i0 + 3] = excl + v0 + v1 + v2; }
        __syncthreads();
        if (tid == 0) carry = carryv + wsum[31];
        __syncthreads();
    }
    if (tid == 0) rp[n] = carry;
}

__global__ void scatter_kernel(const int* __restrict__ src, const int* __restrict__ dst,
                               int E, int which) {
    int e = blockIdx.x * blockDim.x + threadIdx.x;
    if (e >= E) return;
    int d = dst[e];
    if (which) { int p = atomicAdd(&g_cur2[d], 1); g_csr2[p] = src[e]; }
    else       { int p = atomicAdd(&g_cur1[d], 1); g_csr1[p] = src[e]; }
}

// ---------------- fp16 conversions ----------------
__global__ void cvt_x_kernel(const float* __restrict__ x) {
    size_t i = (size_t)blockIdx.x * blockDim.x + threadIdx.x;
    const size_t n4 = (size_t)N1 * 128 / 4;
    if (i < n4) {
        float4 v = ((const float4*)x)[i];
        __half2* o = (__half2*)g_xh;
        o[2 * i + 0] = __floats2half2_rn(v.x, v.y);
        o[2 * i + 1] = __floats2half2_rn(v.z, v.w);
    }
}
// transpose weights to [N][K] fp16
__global__ void cvt_w_kernel(const float* __restrict__ W1l, const float* __restrict__ W1r,
                             const float* __restrict__ W2l, const float* __restrict__ W2r) {
    int i = blockIdx.x * blockDim.x + threadIdx.x;
    if (i < 128 * 256) {                  // W1: [K=128][N=256]
        int k = i >> 8, n = i & 255;
        g_w1lt[n * 128 + k] = __float2half(W1l[i]);
        g_w1rt[n * 128 + k] = __float2half(W1r[i]);
    }
    if (i < 256 * 64) {                   // W2: [K=256][N=64]
        int k = i >> 6, n = i & 63;
        g_w2lt[n * 256 + k] = __float2half(W2l[i]);
        g_w2rt[n * 256 + k] = __float2half(W2r[i]);
    }
}

// ---------------- fp16 mma helper ----------------
__device__ __forceinline__ void mma_f16(float* d, const unsigned* a, const unsigned* b) {
    asm volatile("mma.sync.aligned.m16n8k16.row.col.f32.f16.f16.f32 "
        "{%0,%1,%2,%3}, {%4,%5,%6,%7}, {%8,%9}, {%0,%1,%2,%3};"
        : "+f"(d[0]), "+f"(d[1]), "+f"(d[2]), "+f"(d[3])
        : "r"(a[0]), "r"(a[1]), "r"(a[2]), "r"(a[3]), "r"(b[0]), "r"(b[1]));
}

// ---------------- layer-1 GEMM: C[M,256] = Ah[M,128] @ Bt[256,128]^T + bias ----------------
// BM=128, full N=256, BK=32, 512 threads (16 warps, 4M x 4N), warp tile 32x64.
// out_half: 1 -> __half C (g_xl1h), 0 -> float C (g_xr1)
__global__ __launch_bounds__(512) void gemm_f16_l1(
    const __half* __restrict__ A, const __half* __restrict__ Bt,
    const float* __restrict__ bias, void* __restrict__ Cout,
    int M, int out_half)
{
    __shared__ __half As[128][40];
    __shared__ __half Bs[256][40];
    const int K = 128;
    int tid = threadIdx.x;
    int lane = tid & 31, warp = tid >> 5;
    int wm = warp & 3, wn = warp >> 2;
    int g = lane >> 2, t = lane & 3;
    int bm = blockIdx.x * 128;

    float acc[2][8][4];
    #pragma unroll
    for (int mi = 0; mi < 2; mi++)
        #pragma unroll
        for (int ni = 0; ni < 8; ni++)
            #pragma unroll
            for (int j = 0; j < 4; j++) acc[mi][ni][j] = 0.f;

    for (int k0 = 0; k0 < K; k0 += 32) {
        {   // A tile 128x32 halves
            int row = tid >> 2, seg = (tid & 3) * 8;
            int gr = bm + row;
            uint4 v = make_uint4(0u, 0u, 0u, 0u);
            if (gr < M) v = *(const uint4*)(A + (size_t)gr * K + k0 + seg);
            *(uint4*)&As[row][seg] = v;
        }
        #pragma unroll
        for (int p = 0; p < 2; p++) {   // B tile 256x32 halves
            int idx = tid + p * 512;
            int row = idx >> 2, seg = (idx & 3) * 8;
            *(uint4*)&Bs[row][seg] = *(const uint4*)(Bt + (size_t)row * K + k0 + seg);
        }
        __syncthreads();
        #pragma unroll
        for (int kk = 0; kk < 32; kk += 16) {
            unsigned af[2][4], bf[8][2];
            #pragma unroll
            for (int mi = 0; mi < 2; mi++) {
                int m0 = wm * 32 + mi * 16;
                af[mi][0] = *(const unsigned*)&As[m0 + g    ][kk + 2 * t];
                af[mi][1] = *(const unsigned*)&As[m0 + g + 8][kk + 2 * t];
                af[mi][2] = *(const unsigned*)&As[m0 + g    ][kk + 2 * t + 8];
                af[mi][3] = *(const unsigned*)&As[m0 + g + 8][kk + 2 * t + 8];
            }
            #pragma unroll
            for (int ni = 0; ni < 8; ni++) {
                int n0 = wn * 64 + ni * 8;
                bf[ni][0] = *(const unsigned*)&Bs[n0 + g][kk + 2 * t];
                bf[ni][1] = *(const unsigned*)&Bs[n0 + g][kk + 2 * t + 8];
            }
            #pragma unroll
            for (int mi = 0; mi < 2; mi++)
                #pragma unroll
                for (int ni = 0; ni < 8; ni++)
                    mma_f16(acc[mi][ni], af[mi], bf[ni]);
        }
        __syncthreads();
    }

    #pragma unroll
    for (int mi = 0; mi < 2; mi++) {
        #pragma unroll
        for (int ni = 0; ni < 8; ni++) {
            int col = wn * 64 + ni * 8 + 2 * t;
            float2 bb = *(const float2*)(bias + col);
            int r0 = bm + wm * 32 + mi * 16 + g;
            int r1 = r0 + 8;
            if (out_half) {
                __half* C = (__half*)Cout;
                if (r0 < M)
                    *(__half2*)(C + (size_t)r0 * 256 + col) =
                        __floats2half2_rn(acc[mi][ni][0] + bb.x, acc[mi][ni][1] + bb.y);
                if (r1 < M)
                    *(__half2*)(C + (size_t)r1 * 256 + col) =
                        __floats2half2_rn(acc[mi][ni][2] + bb.x, acc[mi][ni][3] + bb.y);
            } else {
                float* C = (float*)Cout;
                if (r0 < M)
                    *(float2*)(C + (size_t)r0 * 256 + col) =
                        make_float2(acc[mi][ni][0] + bb.x, acc[mi][ni][1] + bb.y);
                if (r1 < M)
                    *(float2*)(C + (size_t)r1 * 256 + col) =
                        make_float2(acc[mi][ni][2] + bb.x, acc[mi][ni][3] + bb.y);
            }
        }
    }
}

// ---------------- layer-2 GEMM: C[M,64] = relu(bn(A[M,256])) @ Bt[64,256]^T + bias ----------------
// BM=128, full N=64, BK=32, 256 threads (8 warps, 4M x 2N), warp tile 32x32.
__global__ __launch_bounds__(256) void gemm_f16_l2(
    const float* __restrict__ A, const __half* __restrict__ Bt,
    const float* __restrict__ bias, float* __restrict__ C, int M)
{
    __shared__ __half As[128][40];
    __shared__ __half Bs[64][40];
    const int K = 256;
    int tid = threadIdx.x;
    int lane = tid & 31, warp = tid >> 5;
    int wm = warp & 3, wn = warp >> 2;
    int g = lane >> 2, t = lane & 3;
    int bm = blockIdx.x * 128;

    float acc[2][4][4];
    #pragma unroll
    for (int mi = 0; mi < 2; mi++)
        #pragma unroll
        for (int ni = 0; ni < 4; ni++)
            #pragma unroll
            for (int j = 0; j < 4; j++) acc[mi][ni][j] = 0.f;

    for (int k0 = 0; k0 < K; k0 += 32) {
        int colA = (tid & 7) * 4;
        float4 sc = *(const float4*)(g_bn_scale + k0 + colA);
        float4 sh = *(const float4*)(g_bn_shift + k0 + colA);
        #pragma unroll
        for (int p = 0; p < 4; p++) {   // A tile 128x32 fp32 -> BN+ReLU -> fp16
            int row = (tid >> 3) + p * 32;
            int gr = bm + row;
            float4 v = (gr < M) ? *(const float4*)(A + (size_t)gr * K + k0 + colA)
                                : make_float4(0.f, 0.f, 0.f, 0.f);
            v.x = fmaxf(v.x * sc.x + sh.x, 0.f);
            v.y = fmaxf(v.y * sc.y + sh.y, 0.f);
            v.z = fmaxf(v.z * sc.z + sh.z, 0.f);
            v.w = fmaxf(v.w * sc.w + sh.w, 0.f);
            *(__half2*)&As[row][colA]     = __floats2half2_rn(v.x, v.y);
            *(__half2*)&As[row][colA + 2] = __floats2half2_rn(v.z, v.w);
        }
        {   // B tile 64x32 halves
            int row = tid >> 2, seg = (tid & 3) * 8;
            *(uint4*)&Bs[row][seg] = *(const uint4*)(Bt + (size_t)row * K + k0 + seg);
        }
        __syncthreads();
        #pragma unroll
        for (int kk = 0; kk < 32; kk += 16) {
            unsigned af[2][4], bf[4][2];
            #pragma unroll
            for (int mi = 0; mi < 2; mi++) {
                int m0 = wm * 32 + mi * 16;
                af[mi][0] = *(const unsigned*)&As[m0 + g    ][kk + 2 * t];
                af[mi][1] = *(const unsigned*)&As[m0 + g + 8][kk + 2 * t];
                af[mi][2] = *(const unsigned*)&As[m0 + g    ][kk + 2 * t + 8];
                af[mi][3] = *(const unsigned*)&As[m0 + g + 8][kk + 2 * t + 8];
            }
            #pragma unroll
            for (int ni = 0; ni < 4; ni++) {
                int n0 = wn * 32 + ni * 8;
                bf[ni][0] = *(const unsigned*)&Bs[n0 + g][kk + 2 * t];
                bf[ni][1] = *(const unsigned*)&Bs[n0 + g][kk + 2 * t + 8];
            }
            #pragma unroll
            for (int mi = 0; mi < 2; mi++)
                #pragma unroll
                for (int ni = 0; ni < 4; ni++)
                    mma_f16(acc[mi][ni], af[mi], bf[ni]);
        }
        __syncthreads();
    }

    #pragma unroll
    for (int mi = 0; mi < 2; mi++) {
        #pragma unroll
        for (int ni = 0; ni < 4; ni++) {
            int col = wn * 32 + ni * 8 + 2 * t;
            float2 bb = *(const float2*)(bias + col);
            int r0 = bm + wm * 32 + mi * 16 + g;
            int r1 = r0 + 8;
            if (r0 < M)
                *(float2*)(C + (size_t)r0 * 64 + col) =
                    make_float2(acc[mi][ni][0] + bb.x, acc[mi][ni][1] + bb.y);
            if (r1 < M)
                *(float2*)(C + (size_t)r1 * 64 + col) =
                    make_float2(acc[mi][ni][2] + bb.x, acc[mi][ni][3] + bb.y);
        }
    }
}

// ---------------- layer-1 fused edge kernel (fp16 gather table) ----------------
__global__ __launch_bounds__(256) void edge1_kernel(const float* __restrict__ att,
                                                    const float* __restrict__ bias)
{
    int w = (blockIdx.x * 256 + threadIdx.x) >> 5;
    int lane = threadIdx.x & 31;
    if (w >= N2) return;
    int off = lane * 8;

    const float* xrp = g_xr1 + (size_t)w * D1 + off;
    float4 xrA = *(const float4*)xrp;
    float4 xrB = *(const float4*)(xrp + 4);
    float4 atA = *(const float4*)(att + off);
    float4 atB = *(const float4*)(att + off + 4);

    float m = -INFINITY, s = 0.f;
    float ac[8] = {0.f, 0.f, 0.f, 0.f, 0.f, 0.f, 0.f, 0.f};

    int jb = g_rp1[w], je = g_rp1[w + 1];
    for (int j = jb; j < je; ++j) {
        int src = g_csr1[j];
        uint4 raw = *(const uint4*)(g_xl1h + (size_t)src * D1 + off);
        float2 f0 = __half22float2(*reinterpret_cast<const __half2*>(&raw.x));
        float2 f1 = __half22float2(*reinterpret_cast<const __half2*>(&raw.y));
        float2 f2 = __half22float2(*reinterpret_cast<const __half2*>(&raw.z));
        float2 f3 = __half22float2(*reinterpret_cast<const __half2*>(&raw.w));
        float p =
            lrelu(f0.x + xrA.x) * atA.x + lrelu(f0.y + xrA.y) * atA.y +
            lrelu(f1.x + xrA.z) * atA.z + lrelu(f1.y + xrA.w) * atA.w +
            lrelu(f2.x + xrB.x) * atB.x + lrelu(f2.y + xrB.y) * atB.y +
            lrelu(f3.x + xrB.z) * atB.z + lrelu(f3.y + xrB.w) * atB.w;
        p += __shfl_xor_sync(FULLM, p, 1);
        p += __shfl_xor_sync(FULLM, p, 2);
        p += __shfl_xor_sync(FULLM, p, 4);
        float nm = fmaxf(m, p);
        float sc = __expf(m - nm);
        float wg = __expf(p - nm);
        s = s * sc + wg;
        ac[0] = ac[0] * sc + wg * f0.x; ac[1] = ac[1] * sc + wg * f0.y;
        ac[2] = ac[2] * sc + wg * f1.x; ac[3] = ac[3] * sc + wg * f1.y;
        ac[4] = ac[4] * sc + wg * f2.x; ac[5] = ac[5] * sc + wg * f2.y;
        ac[6] = ac[6] * sc + wg * f3.x; ac[7] = ac[7] * sc + wg * f3.y;
        m = nm;
    }
    float inv = 1.f / (s + SM_EPS);
    float4 bA = *(const float4*)(bias + off);
    float4 bB = *(const float4*)(bias + off + 4);
    float4 o0 = make_float4(ac[0] * inv + bA.x, ac[1] * inv + bA.y,
                            ac[2] * inv + bA.z, ac[3] * inv + bA.w);
    float4 o1 = make_float4(ac[4] * inv + bB.x, ac[5] * inv + bB.y,
                            ac[6] * inv + bB.z, ac[7] * inv + bB.w);
    float* hp = g_h + (size_t)w * D1 + off;
    *(float4*)hp = o0;
    *(float4*)(hp + 4) = o1;
}

// ---------------- batchnorm statistics (single pass) ----------------
__global__ void bn_stats_kernel() {
    int col = threadIdx.x;
    float s = 0.f, q = 0.f;
    for (int r = blockIdx.x; r < N2; r += gridDim.x) {
        float v = g_h[(size_t)r * D1 + col];
        s += v;
        q += v * v;
    }
    atomicAdd(&g_bn_sum[col], s);
    atomicAdd(&g_bn_sqs[col], q);
}
__global__ void bn_final_kernel(const float* __restrict__ gamma, const float* __restrict__ beta) {
    int c = threadIdx.x;
    float mu = g_bn_sum[c] * (1.f / N2);
    float var = g_bn_sqs[c] * (1.f / N2) - mu * mu;
    var = fmaxf(var, 0.f);
    float sc = gamma[c] * rsqrtf(var + BN_EPS);
    g_bn_scale[c] = sc;
    g_bn_shift[c] = beta[c] - mu * sc;
}

// ---------------- layer-2 fused edge kernel + log_softmax ----------------
__global__ __launch_bounds__(256) void edge2_kernel(const float* __restrict__ att,
                                                    const float* __restrict__ bias,
                                                    float* __restrict__ out)
{
    int w = (blockIdx.x * 256 + threadIdx.x) >> 5;
    int lane = threadIdx.x & 31;
    if (w >= N3) return;
    int off = lane * 2;

    float2 xr = *(const float2*)(g_xr2 + (size_t)w * D2 + off);
    float2 at = *(const float2*)(att + off);
    float m = -INFINITY, s = 0.f, a0 = 0.f, a1 = 0.f;

    int jb = g_rp2[w], je = g_rp2[w + 1];
    for (int j = jb; j < je; ++j) {
        int src = g_csr2[j];
        float2 xj = *(const float2*)(g_xl2 + (size_t)src * D2 + off);
        float p = lrelu(xj.x + xr.x) * at.x + lrelu(xj.y + xr.y) * at.y;
        #pragma unroll
        for (int o = 16; o > 0; o >>= 1) p += __shfl_xor_sync(FULLM, p, o);
        float nm = fmaxf(m, p);
        float sc = __expf(m - nm);
        float wg = __expf(p - nm);
        s = s * sc + wg;
        a0 = a0 * sc + wg * xj.x;
        a1 = a1 * sc + wg * xj.y;
        m = nm;
    }
    float inv = 1.f / (s + SM_EPS);
    float o0 = a0 * inv + bias[off];
    float o1 = a1 * inv + bias[off + 1];

    float mx = fmaxf(o0, o1);
    #pragma unroll
    for (int o = 16; o > 0; o >>= 1) mx = fmaxf(mx, __shfl_xor_sync(FULLM, mx, o));
    float se = __expf(o0 - mx) + __expf(o1 - mx);
    #pragma unroll
    for (int o = 16; o > 0; o >>= 1) se += __shfl_xor_sync(FULLM, se, o);
    float lse = __logf(se);
    float2 r = make_float2(o0 - mx - lse, o1 - mx - lse);
    *(float2*)(out + (size_t)w * D2 + off) = r;
}

// ---------------- launch ----------------
extern "C" void kernel_launch(void* const* d_in, const int* in_sizes, int n_in,
                              void* d_out, int out_size)
{
    const float* x       = (const float*)d_in[0];
    const int*   ei1_src = (const int*)d_in[1];
    const int*   ei1_dst = (const int*)d_in[2];
    const int*   ei2_src = (const int*)d_in[3];
    const int*   ei2_dst = (const int*)d_in[4];
    const float* W1l     = (const float*)d_in[5];
    const float* b1l     = (const float*)d_in[6];
    const float* W1r     = (const float*)d_in[7];
    const float* b1r     = (const float*)d_in[8];
    const float* att1    = (const float*)d_in[9];
    const float* bias1   = (const float*)d_in[10];
    const float* gamma   = (const float*)d_in[11];
    const float* beta    = (const float*)d_in[12];
    const float* W2l     = (const float*)d_in[13];
    const float* b2l     = (const float*)d_in[14];
    const float* W2r     = (const float*)d_in[15];
    const float* b2r     = (const float*)d_in[16];
    const float* att2    = (const float*)d_in[17];
    const float* bias2   = (const float*)d_in[18];
    float* out = (float*)d_out;

    __half *p_xh, *p_xl1h, *p_w1lt, *p_w1rt, *p_w2lt, *p_w2rt;
    float *p_xr1, *p_h, *p_xl2, *p_xr2;
    cudaGetSymbolAddress((void**)&p_xh,   g_xh);
    cudaGetSymbolAddress((void**)&p_xl1h, g_xl1h);
    cudaGetSymbolAddress((void**)&p_w1lt, g_w1lt);
    cudaGetSymbolAddress((void**)&p_w1rt, g_w1rt);
    cudaGetSymbolAddress((void**)&p_w2lt, g_w2lt);
    cudaGetSymbolAddress((void**)&p_w2rt, g_w2rt);
    cudaGetSymbolAddress((void**)&p_xr1, g_xr1);
    cudaGetSymbolAddress((void**)&p_h,   g_h);
    cudaGetSymbolAddress((void**)&p_xl2, g_xl2);
    cudaGetSymbolAddress((void**)&p_xr2, g_xr2);

    // CSR build
    zero_kernel<<<(N2 + 255) / 256, 256>>>();
    hist_kernel<<<(E1 + 255) / 256, 256>>>(ei1_dst, ei2_dst);
    scan2_kernel<<<2, 1024>>>();
    scatter_kernel<<<(E1 + 255) / 256, 256>>>(ei1_src, ei1_dst, E1, 0);
    scatter_kernel<<<(E2 + 255) / 256, 256>>>(ei2_src, ei2_dst, E2, 1);

    // fp16 conversions
    cvt_x_kernel<<<(N1 * 128 / 4 + 511) / 512, 512>>>(x);
    cvt_w_kernel<<<(128 * 256 + 255) / 256, 256>>>(W1l, W1r, W2l, W2r);

    // layer 1 projections (fp16 mma)
    gemm_f16_l1<<<N1 / 128, 512>>>(p_xh, p_w1lt, b1l, p_xl1h, N1, 1);
    gemm_f16_l1<<<(N2 + 127) / 128, 512>>>(p_xh, p_w1rt, b1r, p_xr1, N2, 0);

    // layer 1 attention + aggregation
    edge1_kernel<<<(N2 * 32 + 255) / 256, 256>>>(att1, bias1);

    // batchnorm stats (apply fused into layer-2 GEMM A loads)
    bn_stats_kernel<<<256, 256>>>();
    bn_final_kernel<<<1, 256>>>(gamma, beta);

    // layer 2 projections (BN+ReLU fused, fp16 mma)
    gemm_f16_l2<<<(N2 + 127) / 128, 256>>>(p_h, p_w2lt, b2l, p_xl2, N2);
    gemm_f16_l2<<<(N3 + 127) / 128, 256>>>(p_h, p_w2rt, b2r, p_xr2, N3);

    // layer 2 attention + aggregation + log_softmax
    edge2_kernel<<<(N3 * 32 + 255) / 256, 256>>>(att2, bias2, out);
}

// round 7
// speedup vs baseline: 1.9122x; 1.0613x over previous
#include <cuda_runtime.h>
#include <cuda_bf16.h>
#include <cuda_fp16.h>
#include <math.h>

// ---------------- problem constants ----------------
#define N1 160000
#define N2 40000
#define N3 10000
#define E1 800000
#define E2 200000
#define D1 256          // H1*HID
#define D2 64           // OUT
#define NEG_SLOPE 0.2f
#define BN_EPS 1e-5f
#define SM_EPS 1e-16f
#define FULLM 0xFFFFFFFFu

// ---------------- device scratch (allocation-free) ----------------
__device__ __half g_xl1h[(size_t)N1 * D1];   // 82 MB  fp16 gather table
__device__ float  g_xr1[(size_t)N2 * D1];    // 41 MB
__device__ float  g_h  [(size_t)N2 * D1];    // 41 MB  (layer1 out, pre-BN)
__device__ float  g_xl2[(size_t)N2 * D2];    // 10.2 MB
__device__ float  g_xr2[(size_t)N3 * D2];    // 2.6 MB

__device__ __half g_w1lt[D1 * 128];          // [N=256][K=128]
__device__ __half g_w1rt[D1 * 128];
__device__ __half g_w2lt[D2 * D1];           // [N=64][K=256]
__device__ __half g_w2rt[D2 * D1];

__device__ int g_cnt1[N2];
__device__ int g_rp1 [N2 + 1];
__device__ int g_cur1[N2];
__device__ int g_csr1[E1];

__device__ int g_cnt2[N3];
__device__ int g_rp2 [N3 + 1];
__device__ int g_cur2[N3];
__device__ int g_csr2[E2];

__device__ float g_bn_sum[D1];
__device__ float g_bn_sqs[D1];
__device__ float g_bn_scale[D1];
__device__ float g_bn_shift[D1];

__device__ __forceinline__ float lrelu(float v) { return v > 0.f ? v : NEG_SLOPE * v; }

// ---------------- CSR build ----------------
__global__ void zero_kernel() {
    int i = blockIdx.x * blockDim.x + threadIdx.x;
    if (i < N2) g_cnt1[i] = 0;
    if (i < N3) g_cnt2[i] = 0;
    if (i < D1) { g_bn_sum[i] = 0.f; g_bn_sqs[i] = 0.f; }
}

__global__ void hist_kernel(const int* __restrict__ d1, const int* __restrict__ d2) {
    int i = blockIdx.x * blockDim.x + threadIdx.x;
    if (i < E1) atomicAdd(&g_cnt1[d1[i]], 1);
    if (i < E2) atomicAdd(&g_cnt2[d2[i]], 1);
}

// 2-block warp-shuffle exclusive scan: blockIdx 0 -> layer1 (N2), 1 -> layer2 (N3)
__global__ __launch_bounds__(1024) void scan2_kernel() {
    int which = blockIdx.x;
    const int* cnt = which ? g_cnt2 : g_cnt1;
    int* rp  = which ? g_rp2  : g_rp1;
    int* cur = which ? g_cur2 : g_cur1;
    int n    = which ? N3     : N2;

    __shared__ int wsum[32];
    __shared__ int carry;
    int tid = threadIdx.x;
    int lane = tid & 31, wid = tid >> 5;
    if (tid == 0) carry = 0;
    __syncthreads();

    for (int base = 0; base < n; base += 4096) {
        int i0 = base + tid * 4;
        int v0 = (i0 + 0 < n) ? cnt[i0 + 0] : 0;
        int v1 = (i0 + 1 < n) ? cnt[i0 + 1] : 0;
        int v2 = (i0 + 2 < n) ? cnt[i0 + 2] : 0;
        int v3 = (i0 + 3 < n) ? cnt[i0 + 3] : 0;
        int tot = v0 + v1 + v2 + v3;
        int isum = tot;
        #pragma unroll
        for (int off = 1; off < 32; off <<= 1) {
            int t = __shfl_up_sync(FULLM, isum, off);
            if (lane >= off) isum += t;
        }
        if (lane == 31) wsum[wid] = isum;
        __syncthreads();
        if (wid == 0) {
            int s = wsum[lane];
            #pragma unroll
            for (int off = 1; off < 32; off <<= 1) {
                int t = __shfl_up_sync(FULLM, s, off);
                if (lane >= off) s += t;
            }
            wsum[lane] = s;
        }
        __syncthreads();
        int carryv = carry;
        int woff = (wid > 0) ? wsum[wid - 1] : 0;
        int excl = carryv + woff + (isum - tot);
        if (i0 + 0 < n) { rp[i0 + 0] = excl;                cur[i0 + 0] = excl; }
        if (i0 + 1 < n) { rp[i0 + 1] = excl + v0;           cur[i0 + 1] = excl + v0; }
        if (i0 + 2 < n) { rp[i0 + 2] = excl + v0 + v1;      cur[i0 + 2] = excl + v0 + v1; }
        if (i0 + 3 < n) { rp[i0 + 3] = excl + v0 + v1 + v2; cur[i0 + 3] = excl + v0 + v1 + v2; }
        __syncthreads();
        if (tid == 0) carry = carryv + wsum[31];
        __syncthreads();
    }
    if (tid == 0) rp[n] = carry;
}

// merged scatter for both edge lists
__global__ void scatter_kernel(const int* __restrict__ src1, const int* __restrict__ dst1,
                               const int* __restrict__ src2, const int* __restrict__ dst2) {
    int e = blockIdx.x * blockDim.x + threadIdx.x;
    if (e < E1) { int p = atomicAdd(&g_cur1[dst1[e]], 1); g_csr1[p] = src1[e]; }
    if (e < E2) { int p = atomicAdd(&g_cur2[dst2[e]], 1); g_csr2[p] = src2[e]; }
}

// transpose weights to [N][K] fp16
__global__ void cvt_w_kernel(const float* __restrict__ W1l, const float* __restrict__ W1r,
                             const float* __restrict__ W2l, const float* __restrict__ W2r) {
    int i = blockIdx.x * blockDim.x + threadIdx.x;
    if (i < 128 * 256) {                  // W1: [K=128][N=256]
        int k = i >> 8, n = i & 255;
        g_w1lt[n * 128 + k] = __float2half(W1l[i]);
        g_w1rt[n * 128 + k] = __float2half(W1r[i]);
    }
    if (i < 256 * 64) {                   // W2: [K=256][N=64]
        int k = i >> 6, n = i & 63;
        g_w2lt[n * 256 + k] = __float2half(W2l[i]);
        g_w2rt[n * 256 + k] = __float2half(W2r[i]);
    }
}

// ---------------- fp16 mma helper ----------------
__device__ __forceinline__ void mma_f16(float* d, const unsigned* a, const unsigned* b) {
    asm volatile("mma.sync.aligned.m16n8k16.row.col.f32.f16.f16.f32 "
        "{%0,%1,%2,%3}, {%4,%5,%6,%7}, {%8,%9}, {%0,%1,%2,%3};"
        : "+f"(d[0]), "+f"(d[1]), "+f"(d[2]), "+f"(d[3])
        : "r"(a[0]), "r"(a[1]), "r"(a[2]), "r"(a[3]), "r"(b[0]), "r"(b[1]));
}

__device__ __forceinline__ uint4 pack_f8_to_h8(float4 v0, float4 v1) {
    __half2 h0 = __floats2half2_rn(v0.x, v0.y);
    __half2 h1 = __floats2half2_rn(v0.z, v0.w);
    __half2 h2 = __floats2half2_rn(v1.x, v1.y);
    __half2 h3 = __floats2half2_rn(v1.z, v1.w);
    uint4 u;
    u.x = *(unsigned*)&h0; u.y = *(unsigned*)&h1;
    u.z = *(unsigned*)&h2; u.w = *(unsigned*)&h3;
    return u;
}

// ---------------- layer-1 GEMM: C[M,256] = A_fp32[M,128] @ Bt[256,128]^T + bias ----------------
// BM=128, full N=256, BK=32, 512 threads (16 warps, 4M x 4N), warp tile 32x64.
// A converted fp32->fp16 during smem staging (no separate cvt pass).
// out_half: 1 -> __half C (g_xl1h), 0 -> float C (g_xr1)
__global__ __launch_bounds__(512) void gemm_f16_l1(
    const float* __restrict__ A, const __half* __restrict__ Bt,
    const float* __restrict__ bias, void* __restrict__ Cout,
    int M, int out_half)
{
    __shared__ __half As[128][40];
    __shared__ __half Bs[256][40];
    const int K = 128;
    int tid = threadIdx.x;
    int lane = tid & 31, warp = tid >> 5;
    int wm = warp & 3, wn = warp >> 2;
    int g = lane >> 2, t = lane & 3;
    int bm = blockIdx.x * 128;

    float acc[2][8][4];
    #pragma unroll
    for (int mi = 0; mi < 2; mi++)
        #pragma unroll
        for (int ni = 0; ni < 8; ni++)
            #pragma unroll
            for (int j = 0; j < 4; j++) acc[mi][ni][j] = 0.f;

    for (int k0 = 0; k0 < K; k0 += 32) {
        {   // A tile 128x32: fp32 load, convert to fp16 in staging
            int row = tid >> 2, seg = (tid & 3) * 8;
            int gr = bm + row;
            float4 v0 = make_float4(0.f, 0.f, 0.f, 0.f), v1 = v0;
            if (gr < M) {
                const float* ap = A + (size_t)gr * K + k0 + seg;
                v0 = *(const float4*)ap;
                v1 = *(const float4*)(ap + 4);
            }
            *(uint4*)&As[row][seg] = pack_f8_to_h8(v0, v1);
        }
        #pragma unroll
        for (int p = 0; p < 2; p++) {   // B tile 256x32 halves
            int idx = tid + p * 512;
            int row = idx >> 2, seg = (idx & 3) * 8;
            *(uint4*)&Bs[row][seg] = *(const uint4*)(Bt + (size_t)row * K + k0 + seg);
        }
        __syncthreads();
        #pragma unroll
        for (int kk = 0; kk < 32; kk += 16) {
            unsigned af[2][4], bf[8][2];
            #pragma unroll
            for (int mi = 0; mi < 2; mi++) {
                int m0 = wm * 32 + mi * 16;
                af[mi][0] = *(const unsigned*)&As[m0 + g    ][kk + 2 * t];
                af[mi][1] = *(const unsigned*)&As[m0 + g + 8][kk + 2 * t];
                af[mi][2] = *(const unsigned*)&As[m0 + g    ][kk + 2 * t + 8];
                af[mi][3] = *(const unsigned*)&As[m0 + g + 8][kk + 2 * t + 8];
            }
            #pragma unroll
            for (int ni = 0; ni < 8; ni++) {
                int n0 = wn * 64 + ni * 8;
                bf[ni][0] = *(const unsigned*)&Bs[n0 + g][kk + 2 * t];
                bf[ni][1] = *(const unsigned*)&Bs[n0 + g][kk + 2 * t + 8];
            }
            #pragma unroll
            for (int mi = 0; mi < 2; mi++)
                #pragma unroll
                for (int ni = 0; ni < 8; ni++)
                    mma_f16(acc[mi][ni], af[mi], bf[ni]);
        }
        __syncthreads();
    }

    #pragma unroll
    for (int mi = 0; mi < 2; mi++) {
        #pragma unroll
        for (int ni = 0; ni < 8; ni++) {
            int col = wn * 64 + ni * 8 + 2 * t;
            float2 bb = *(const float2*)(bias + col);
            int r0 = bm + wm * 32 + mi * 16 + g;
            int r1 = r0 + 8;
            if (out_half) {
                __half* C = (__half*)Cout;
                if (r0 < M)
                    *(__half2*)(C + (size_t)r0 * 256 + col) =
                        __floats2half2_rn(acc[mi][ni][0] + bb.x, acc[mi][ni][1] + bb.y);
                if (r1 < M)
                    *(__half2*)(C + (size_t)r1 * 256 + col) =
                        __floats2half2_rn(acc[mi][ni][2] + bb.x, acc[mi][ni][3] + bb.y);
            } else {
                float* C = (float*)Cout;
                if (r0 < M)
                    *(float2*)(C + (size_t)r0 * 256 + col) =
                        make_float2(acc[mi][ni][0] + bb.x, acc[mi][ni][1] + bb.y);
                if (r1 < M)
                    *(float2*)(C + (size_t)r1 * 256 + col) =
                        make_float2(acc[mi][ni][2] + bb.x, acc[mi][ni][3] + bb.y);
            }
        }
    }
}

// ---------------- layer-2 GEMM: C[M,64] = relu(bn(A[M,256])) @ Bt[64,256]^T + bias ----------------
__global__ __launch_bounds__(256) void gemm_f16_l2(
    const float* __restrict__ A, const __half* __restrict__ Bt,
    const float* __restrict__ bias, float* __restrict__ C, int M)
{
    __shared__ __half As[128][40];
    __shared__ __half Bs[64][40];
    const int K = 256;
    int tid = threadIdx.x;
    int lane = tid & 31, warp = tid >> 5;
    int wm = warp & 3, wn = warp >> 2;
    int g = lane >> 2, t = lane & 3;
    int bm = blockIdx.x * 128;

    float acc[2][4][4];
    #pragma unroll
    for (int mi = 0; mi < 2; mi++)
        #pragma unroll
        for (int ni = 0; ni < 4; ni++)
            #pragma unroll
            for (int j = 0; j < 4; j++) acc[mi][ni][j] = 0.f;

    for (int k0 = 0; k0 < K; k0 += 32) {
        int colA = (tid & 7) * 4;
        float4 sc = *(const float4*)(g_bn_scale + k0 + colA);
        float4 sh = *(const float4*)(g_bn_shift + k0 + colA);
        #pragma unroll
        for (int p = 0; p < 4; p++) {   // A tile 128x32 fp32 -> BN+ReLU -> fp16
            int row = (tid >> 3) + p * 32;
            int gr = bm + row;
            float4 v = (gr < M) ? *(const float4*)(A + (size_t)gr * K + k0 + colA)
                                : make_float4(0.f, 0.f, 0.f, 0.f);
            v.x = fmaxf(v.x * sc.x + sh.x, 0.f);
            v.y = fmaxf(v.y * sc.y + sh.y, 0.f);
            v.z = fmaxf(v.z * sc.z + sh.z, 0.f);
            v.w = fmaxf(v.w * sc.w + sh.w, 0.f);
            *(__half2*)&As[row][colA]     = __floats2half2_rn(v.x, v.y);
            *(__half2*)&As[row][colA + 2] = __floats2half2_rn(v.z, v.w);
        }
        {   // B tile 64x32 halves
            int row = tid >> 2, seg = (tid & 3) * 8;
            *(uint4*)&Bs[row][seg] = *(const uint4*)(Bt + (size_t)row * K + k0 + seg);
        }
        __syncthreads();
        #pragma unroll
        for (int kk = 0; kk < 32; kk += 16) {
            unsigned af[2][4], bf[4][2];
            #pragma unroll
            for (int mi = 0; mi < 2; mi++) {
                int m0 = wm * 32 + mi * 16;
                af[mi][0] = *(const unsigned*)&As[m0 + g    ][kk + 2 * t];
                af[mi][1] = *(const unsigned*)&As[m0 + g + 8][kk + 2 * t];
                af[mi][2] = *(const unsigned*)&As[m0 + g    ][kk + 2 * t + 8];
                af[mi][3] = *(const unsigned*)&As[m0 + g + 8][kk + 2 * t + 8];
            }
            #pragma unroll
            for (int ni = 0; ni < 4; ni++) {
                int n0 = wn * 32 + ni * 8;
                bf[ni][0] = *(const unsigned*)&Bs[n0 + g][kk + 2 * t];
                bf[ni][1] = *(const unsigned*)&Bs[n0 + g][kk + 2 * t + 8];
            }
            #pragma unroll
            for (int mi = 0; mi < 2; mi++)
                #pragma unroll
                for (int ni = 0; ni < 4; ni++)
                    mma_f16(acc[mi][ni], af[mi], bf[ni]);
        }
        __syncthreads();
    }

    #pragma unroll
    for (int mi = 0; mi < 2; mi++) {
        #pragma unroll
        for (int ni = 0; ni < 4; ni++) {
            int col = wn * 32 + ni * 8 + 2 * t;
            float2 bb = *(const float2*)(bias + col);
            int r0 = bm + wm * 32 + mi * 16 + g;
            int r1 = r0 + 8;
            if (r0 < M)
                *(float2*)(C + (size_t)r0 * 64 + col) =
                    make_float2(acc[mi][ni][0] + bb.x, acc[mi][ni][1] + bb.y);
            if (r1 < M)
                *(float2*)(C + (size_t)r1 * 64 + col) =
                    make_float2(acc[mi][ni][2] + bb.x, acc[mi][ni][3] + bb.y);
        }
    }
}

// ---------------- layer-1 fused edge kernel: 4-edge unrolled online softmax ----------------
__global__ __launch_bounds__(256) void edge1_kernel(const float* __restrict__ att,
                                                    const float* __restrict__ bias)
{
    int w = (blockIdx.x * 256 + threadIdx.x) >> 5;
    int lane = threadIdx.x & 31;
    if (w >= N2) return;
    int off = lane * 8;

    float xr[8], at[8];
    {
        const float* xrp = g_xr1 + (size_t)w * D1 + off;
        float4 a = *(const float4*)xrp, b = *(const float4*)(xrp + 4);
        xr[0] = a.x; xr[1] = a.y; xr[2] = a.z; xr[3] = a.w;
        xr[4] = b.x; xr[5] = b.y; xr[6] = b.z; xr[7] = b.w;
        float4 c = *(const float4*)(att + off), d = *(const float4*)(att + off + 4);
        at[0] = c.x; at[1] = c.y; at[2] = c.z; at[3] = c.w;
        at[4] = d.x; at[5] = d.y; at[6] = d.z; at[7] = d.w;
    }

    float m = -INFINITY, s = 0.f;
    float ac[8] = {0.f, 0.f, 0.f, 0.f, 0.f, 0.f, 0.f, 0.f};

    int jb = g_rp1[w], je = g_rp1[w + 1];
    int j = jb;

    // 4-edge unrolled main loop (independent gathers -> MLP 4)
    for (; j + 4 <= je; j += 4) {
        int ss0 = g_csr1[j], ss1 = g_csr1[j + 1], ss2 = g_csr1[j + 2], ss3 = g_csr1[j + 3];
        uint4 r0 = *(const uint4*)(g_xl1h + (size_t)ss0 * D1 + off);
        uint4 r1 = *(const uint4*)(g_xl1h + (size_t)ss1 * D1 + off);
        uint4 r2 = *(const uint4*)(g_xl1h + (size_t)ss2 * D1 + off);
        uint4 r3 = *(const uint4*)(g_xl1h + (size_t)ss3 * D1 + off);

        float f[4][8], p[4];
        uint4 rr[4] = {r0, r1, r2, r3};
        #pragma unroll
        for (int q = 0; q < 4; q++) {
            float2 a = __half22float2(*reinterpret_cast<const __half2*>(&rr[q].x));
            float2 b = __half22float2(*reinterpret_cast<const __half2*>(&rr[q].y));
            float2 c = __half22float2(*reinterpret_cast<const __half2*>(&rr[q].z));
            float2 d = __half22float2(*reinterpret_cast<const __half2*>(&rr[q].w));
            f[q][0] = a.x; f[q][1] = a.y; f[q][2] = b.x; f[q][3] = b.y;
            f[q][4] = c.x; f[q][5] = c.y; f[q][6] = d.x; f[q][7] = d.y;
            float pp = 0.f;
            #pragma unroll
            for (int cIdx = 0; cIdx < 8; cIdx++)
                pp += lrelu(f[q][cIdx] + xr[cIdx]) * at[cIdx];
            pp += __shfl_xor_sync(FULLM, pp, 1);
            pp += __shfl_xor_sync(FULLM, pp, 2);
            pp += __shfl_xor_sync(FULLM, pp, 4);
            p[q] = pp;
        }
        float nm = fmaxf(fmaxf(fmaxf(p[0], p[1]), fmaxf(p[2], p[3])), m);
        float sc = __expf(m - nm);
        float w0 = __expf(p[0] - nm), w1 = __expf(p[1] - nm);
        float w2 = __expf(p[2] - nm), w3 = __expf(p[3] - nm);
        s = s * sc + (w0 + w1) + (w2 + w3);
        #pragma unroll
        for (int cIdx = 0; cIdx < 8; cIdx++) {
            float v = ac[cIdx] * sc;
            v += w0 * f[0][cIdx];
            v += w1 * f[1][cIdx];
            v += w2 * f[2][cIdx];
            v += w3 * f[3][cIdx];
            ac[cIdx] = v;
        }
        m = nm;
    }

    // tail
    for (; j < je; ++j) {
        int src = g_csr1[j];
        uint4 raw = *(const uint4*)(g_xl1h + (size_t)src * D1 + off);
        float2 a = __half22float2(*reinterpret_cast<const __half2*>(&raw.x));
        float2 b = __half22float2(*reinterpret_cast<const __half2*>(&raw.y));
        float2 c = __half22float2(*reinterpret_cast<const __half2*>(&raw.z));
        float2 d = __half22float2(*reinterpret_cast<const __half2*>(&raw.w));
        float f[8] = {a.x, a.y, b.x, b.y, c.x, c.y, d.x, d.y};
        float pp = 0.f;
        #pragma unroll
        for (int cIdx = 0; cIdx < 8; cIdx++)
            pp += lrelu(f[cIdx] + xr[cIdx]) * at[cIdx];
        pp += __shfl_xor_sync(FULLM, pp, 1);
        pp += __shfl_xor_sync(FULLM, pp, 2);
        pp += __shfl_xor_sync(FULLM, pp, 4);
        float nm = fmaxf(m, pp);
        float sc = __expf(m - nm);
        float wg = __expf(pp - nm);
        s = s * sc + wg;
        #pragma unroll
        for (int cIdx = 0; cIdx < 8; cIdx++)
            ac[cIdx] = ac[cIdx] * sc + wg * f[cIdx];
        m = nm;
    }

    float inv = 1.f / (s + SM_EPS);
    float4 bA = *(const float4*)(bias + off);
    float4 bB = *(const float4*)(bias + off + 4);
    float4 o0 = make_float4(ac[0] * inv + bA.x, ac[1] * inv + bA.y,
                            ac[2] * inv + bA.z, ac[3] * inv + bA.w);
    float4 o1 = make_float4(ac[4] * inv + bB.x, ac[5] * inv + bB.y,
                            ac[6] * inv + bB.z, ac[7] * inv + bB.w);
    float* hp = g_h + (size_t)w * D1 + off;
    *(float4*)hp = o0;
    *(float4*)(hp + 4) = o1;
}

// ---------------- batchnorm statistics (single pass) ----------------
__global__ void bn_stats_kernel() {
    int col = threadIdx.x;
    float s = 0.f, q = 0.f;
    for (int r = blockIdx.x; r < N2; r += gridDim.x) {
        float v = g_h[(size_t)r * D1 + col];
        s += v;
        q += v * v;
    }
    atomicAdd(&g_bn_sum[col], s);
    atomicAdd(&g_bn_sqs[col], q);
}
__global__ void bn_final_kernel(const float* __restrict__ gamma, const float* __restrict__ beta) {
    int c = threadIdx.x;
    float mu = g_bn_sum[c] * (1.f / N2);
    float var = g_bn_sqs[c] * (1.f / N2) - mu * mu;
    var = fmaxf(var, 0.f);
    float sc = gamma[c] * rsqrtf(var + BN_EPS);
    g_bn_scale[c] = sc;
    g_bn_shift[c] = beta[c] - mu * sc;
}

// ---------------- layer-2 fused edge kernel + log_softmax ----------------
__global__ __launch_bounds__(256) void edge2_kernel(const float* __restrict__ att,
                                                    const float* __restrict__ bias,
                                                    float* __restrict__ out)
{
    int w = (blockIdx.x * 256 + threadIdx.x) >> 5;
    int lane = threadIdx.x & 31;
    if (w >= N3) return;
    int off = lane * 2;

    float2 xr = *(const float2*)(g_xr2 + (size_t)w * D2 + off);
    float2 at = *(const float2*)(att + off);
    float m = -INFINITY, s = 0.f, a0 = 0.f, a1 = 0.f;

    int jb = g_rp2[w], je = g_rp2[w + 1];
    for (int j = jb; j < je; ++j) {
        int src = g_csr2[j];
        float2 xj = *(const float2*)(g_xl2 + (size_t)src * D2 + off);
        float p = lrelu(xj.x + xr.x) * at.x + lrelu(xj.y + xr.y) * at.y;
        #pragma unroll
        for (int o = 16; o > 0; o >>= 1) p += __shfl_xor_sync(FULLM, p, o);
        float nm = fmaxf(m, p);
        float sc = __expf(m - nm);
        float wg = __expf(p - nm);
        s = s * sc + wg;
        a0 = a0 * sc + wg * xj.x;
        a1 = a1 * sc + wg * xj.y;
        m = nm;
    }
    float inv = 1.f / (s + SM_EPS);
    float o0 = a0 * inv + bias[off];
    float o1 = a1 * inv + bias[off + 1];

    float mx = fmaxf(o0, o1);
    #pragma unroll
    for (int o = 16; o > 0; o >>= 1) mx = fmaxf(mx, __shfl_xor_sync(FULLM, mx, o));
    float se = __expf(o0 - mx) + __expf(o1 - mx);
    #pragma unroll
    for (int o = 16; o > 0; o >>= 1) se += __shfl_xor_sync(FULLM, se, o);
    float lse = __logf(se);
    float2 r = make_float2(o0 - mx - lse, o1 - mx - lse);
    *(float2*)(out + (size_t)w * D2 + off) = r;
}

// ---------------- launch ----------------
extern "C" void kernel_launch(void* const* d_in, const int* in_sizes, int n_in,
                              void* d_out, int out_size)
{
    const float* x       = (const float*)d_in[0];
    const int*   ei1_src = (const int*)d_in[1];
    const int*   ei1_dst = (const int*)d_in[2];
    const int*   ei2_src = (const int*)d_in[3];
    const int*   ei2_dst = (const int*)d_in[4];
    const float* W1l     = (const float*)d_in[5];
    const float* b1l     = (const float*)d_in[6];
    const float* W1r     = (const float*)d_in[7];
    const float* b1r     = (const float*)d_in[8];
    const float* att1    = (const float*)d_in[9];
    const float* bias1   = (const float*)d_in[10];
    const float* gamma   = (const float*)d_in[11];
    const float* beta    = (const float*)d_in[12];
    const float* W2l     = (const float*)d_in[13];
    const float* b2l     = (const float*)d_in[14];
    const float* W2r     = (const float*)d_in[15];
    const float* b2r     = (const float*)d_in[16];
    const float* att2    = (const float*)d_in[17];
    const float* bias2   = (const float*)d_in[18];
    float* out = (float*)d_out;

    __half *p_xl1h, *p_w1lt, *p_w1rt, *p_w2lt, *p_w2rt;
    float *p_xr1, *p_h, *p_xl2, *p_xr2;
    cudaGetSymbolAddress((void**)&p_xl1h, g_xl1h);
    cudaGetSymbolAddress((void**)&p_w1lt, g_w1lt);
    cudaGetSymbolAddress((void**)&p_w1rt, g_w1rt);
    cudaGetSymbolAddress((void**)&p_w2lt, g_w2lt);
    cudaGetSymbolAddress((void**)&p_w2rt, g_w2rt);
    cudaGetSymbolAddress((void**)&p_xr1, g_xr1);
    cudaGetSymbolAddress((void**)&p_h,   g_h);
    cudaGetSymbolAddress((void**)&p_xl2, g_xl2);
    cudaGetSymbolAddress((void**)&p_xr2, g_xr2);

    // CSR build
    zero_kernel<<<(N2 + 255) / 256, 256>>>();
    hist_kernel<<<(E1 + 255) / 256, 256>>>(ei1_dst, ei2_dst);
    scan2_kernel<<<2, 1024>>>();
    scatter_kernel<<<(E1 + 255) / 256, 256>>>(ei1_src, ei1_dst, ei2_src, ei2_dst);

    // weight prep
    cvt_w_kernel<<<(128 * 256 + 255) / 256, 256>>>(W1l, W1r, W2l, W2r);

    // layer 1 projections (fp16 mma, fp32 A staged with inline convert)
    gemm_f16_l1<<<N1 / 128, 512>>>(x, p_w1lt, b1l, p_xl1h, N1, 1);
    gemm_f16_l1<<<(N2 + 127) / 128, 512>>>(x, p_w1rt, b1r, p_xr1, N2, 0);

    // layer 1 attention + aggregation
    edge1_kernel<<<(N2 * 32 + 255) / 256, 256>>>(att1, bias1);

    // batchnorm stats (apply fused into layer-2 GEMM A loads)
    bn_stats_kernel<<<256, 256>>>();
    bn_final_kernel<<<1, 256>>>(gamma, beta);

    // layer 2 projections (BN+ReLU fused, fp16 mma)
    gemm_f16_l2<<<(N2 + 127) / 128, 256>>>(p_h, p_w2lt, b2l, p_xl2, N2);
    gemm_f16_l2<<<(N3 + 127) / 128, 256>>>(p_h, p_w2rt, b2r, p_xr2, N3);

    // layer 2 attention + aggregation + log_softmax
    edge2_kernel<<<(N3 * 32 + 255) / 256, 256>>>(att2, bias2, out);
}

// round 8
// speedup vs baseline: 1.9376x; 1.0133x over previous
#include <cuda_runtime.h>
#include <cuda_bf16.h>
#include <cuda_fp16.h>
#include <math.h>

// ---------------- problem constants ----------------
#define N1 160000
#define N2 40000
#define N3 10000
#define E1 800000
#define E2 200000
#define D1 256          // H1*HID
#define D2 64           // OUT
#define NEG_SLOPE 0.2f
#define BN_EPS 1e-5f
#define SM_EPS 1e-16f
#define FULLM 0xFFFFFFFFu

// ---------------- device scratch (allocation-free) ----------------
__device__ __half g_xl1h[(size_t)N1 * D1];   // 82 MB  fp16 gather table
__device__ float  g_xr1[(size_t)N2 * D1];    // 41 MB
__device__ float  g_h  [(size_t)N2 * D1];    // 41 MB  (layer1 out, pre-BN)
__device__ float  g_xl2[(size_t)N2 * D2];    // 10.2 MB
__device__ float  g_xr2[(size_t)N3 * D2];    // 2.6 MB

__device__ __half g_w1lt[D1 * 128];          // [N=256][K=128]
__device__ __half g_w1rt[D1 * 128];
__device__ __half g_w2lt[D2 * D1];           // [N=64][K=256]
__device__ __half g_w2rt[D2 * D1];

__device__ int g_cnt1[N2];
__device__ int g_rp1 [N2 + 1];
__device__ int g_cur1[N2];
__device__ int g_csr1[E1];

__device__ int g_cnt2[N3];
__device__ int g_rp2 [N3 + 1];
__device__ int g_cur2[N3];
__device__ int g_csr2[E2];

__device__ float g_bn_sum[D1];
__device__ float g_bn_sqs[D1];
__device__ float g_bn_scale[D1];
__device__ float g_bn_shift[D1];

__device__ __forceinline__ float lrelu(float v) { return v > 0.f ? v : NEG_SLOPE * v; }

__device__ __forceinline__ void unpack8(uint4 r, float* f) {
    float2 a = __half22float2(*reinterpret_cast<const __half2*>(&r.x));
    float2 b = __half22float2(*reinterpret_cast<const __half2*>(&r.y));
    float2 c = __half22float2(*reinterpret_cast<const __half2*>(&r.z));
    float2 d = __half22float2(*reinterpret_cast<const __half2*>(&r.w));
    f[0] = a.x; f[1] = a.y; f[2] = b.x; f[3] = b.y;
    f[4] = c.x; f[5] = c.y; f[6] = d.x; f[7] = d.y;
}

// ---------------- CSR build ----------------
__global__ void zero_kernel() {
    int i = blockIdx.x * blockDim.x + threadIdx.x;
    if (i < N2) g_cnt1[i] = 0;
    if (i < N3) g_cnt2[i] = 0;
    if (i < D1) { g_bn_sum[i] = 0.f; g_bn_sqs[i] = 0.f; }
}

// 4 edges per thread (E1, E2 divisible by 4)
__global__ void hist_kernel(const int* __restrict__ d1, const int* __restrict__ d2) {
    int i = (blockIdx.x * blockDim.x + threadIdx.x) * 4;
    if (i < E1) {
        int4 v = *(const int4*)(d1 + i);
        atomicAdd(&g_cnt1[v.x], 1); atomicAdd(&g_cnt1[v.y], 1);
        atomicAdd(&g_cnt1[v.z], 1); atomicAdd(&g_cnt1[v.w], 1);
    }
    if (i < E2) {
        int4 v = *(const int4*)(d2 + i);
        atomicAdd(&g_cnt2[v.x], 1); atomicAdd(&g_cnt2[v.y], 1);
        atomicAdd(&g_cnt2[v.z], 1); atomicAdd(&g_cnt2[v.w], 1);
    }
}

// 2-block warp-shuffle exclusive scan: blockIdx 0 -> layer1 (N2), 1 -> layer2 (N3)
__global__ __launch_bounds__(1024) void scan2_kernel() {
    int which = blockIdx.x;
    const int* cnt = which ? g_cnt2 : g_cnt1;
    int* rp  = which ? g_rp2  : g_rp1;
    int* cur = which ? g_cur2 : g_cur1;
    int n    = which ? N3     : N2;

    __shared__ int wsum[32];
    __shared__ int carry;
    int tid = threadIdx.x;
    int lane = tid & 31, wid = tid >> 5;
    if (tid == 0) carry = 0;
    __syncthreads();

    for (int base = 0; base < n; base += 4096) {
        int i0 = base + tid * 4;
        int v0 = (i0 + 0 < n) ? cnt[i0 + 0] : 0;
        int v1 = (i0 + 1 < n) ? cnt[i0 + 1] : 0;
        int v2 = (i0 + 2 < n) ? cnt[i0 + 2] : 0;
        int v3 = (i0 + 3 < n) ? cnt[i0 + 3] : 0;
        int tot = v0 + v1 + v2 + v3;
        int isum = tot;
        #pragma unroll
        for (int off = 1; off < 32; off <<= 1) {
            int t = __shfl_up_sync(FULLM, isum, off);
            if (lane >= off) isum += t;
        }
        if (lane == 31) wsum[wid] = isum;
        __syncthreads();
        if (wid == 0) {
            int s = wsum[lane];
            #pragma unroll
            for (int off = 1; off < 32; off <<= 1) {
                int t = __shfl_up_sync(FULLM, s, off);
                if (lane >= off) s += t;
            }
            wsum[lane] = s;
        }
        __syncthreads();
        int carryv = carry;
        int woff = (wid > 0) ? wsum[wid - 1] : 0;
        int excl = carryv + woff + (isum - tot);
        if (i0 + 0 < n) { rp[i0 + 0] = excl;                cur[i0 + 0] = excl; }
        if (i0 + 1 < n) { rp[i0 + 1] = excl + v0;           cur[i0 + 1] = excl + v0; }
        if (i0 + 2 < n) { rp[i0 + 2] = excl + v0 + v1;      cur[i0 + 2] = excl + v0 + v1; }
        if (i0 + 3 < n) { rp[i0 + 3] = excl + v0 + v1 + v2; cur[i0 + 3] = excl + v0 + v1 + v2; }
        __syncthreads();
        if (tid == 0) carry = carryv + wsum[31];
        __syncthreads();
    }
    if (tid == 0) rp[n] = carry;
}

// merged + vectorized scatter (4 edges/thread)
__global__ void scatter_kernel(const int* __restrict__ src1, const int* __restrict__ dst1,
                               const int* __restrict__ src2, const int* __restrict__ dst2) {
    int e = (blockIdx.x * blockDim.x + threadIdx.x) * 4;
    if (e < E1) {
        int4 s = *(const int4*)(src1 + e);
        int4 d = *(const int4*)(dst1 + e);
        int p;
        p = atomicAdd(&g_cur1[d.x], 1); g_csr1[p] = s.x;
        p = atomicAdd(&g_cur1[d.y], 1); g_csr1[p] = s.y;
        p = atomicAdd(&g_cur1[d.z], 1); g_csr1[p] = s.z;
        p = atomicAdd(&g_cur1[d.w], 1); g_csr1[p] = s.w;
    }
    if (e < E2) {
        int4 s = *(const int4*)(src2 + e);
        int4 d = *(const int4*)(dst2 + e);
        int p;
        p = atomicAdd(&g_cur2[d.x], 1); g_csr2[p] = s.x;
        p = atomicAdd(&g_cur2[d.y], 1); g_csr2[p] = s.y;
        p = atomicAdd(&g_cur2[d.z], 1); g_csr2[p] = s.z;
        p = atomicAdd(&g_cur2[d.w], 1); g_csr2[p] = s.w;
    }
}

// transpose weights to [N][K] fp16
__global__ void cvt_w_kernel(const float* __restrict__ W1l, const float* __restrict__ W1r,
                             const float* __restrict__ W2l, const float* __restrict__ W2r) {
    int i = blockIdx.x * blockDim.x + threadIdx.x;
    if (i < 128 * 256) {                  // W1: [K=128][N=256]
        int k = i >> 8, n = i & 255;
        g_w1lt[n * 128 + k] = __float2half(W1l[i]);
        g_w1rt[n * 128 + k] = __float2half(W1r[i]);
    }
    if (i < 256 * 64) {                   // W2: [K=256][N=64]
        int k = i >> 6, n = i & 63;
        g_w2lt[n * 256 + k] = __float2half(W2l[i]);
        g_w2rt[n * 256 + k] = __float2half(W2r[i]);
    }
}

// ---------------- fp16 mma helper ----------------
__device__ __forceinline__ void mma_f16(float* d, const unsigned* a, const unsigned* b) {
    asm volatile("mma.sync.aligned.m16n8k16.row.col.f32.f16.f16.f32 "
        "{%0,%1,%2,%3}, {%4,%5,%6,%7}, {%8,%9}, {%0,%1,%2,%3};"
        : "+f"(d[0]), "+f"(d[1]), "+f"(d[2]), "+f"(d[3])
        : "r"(a[0]), "r"(a[1]), "r"(a[2]), "r"(a[3]), "r"(b[0]), "r"(b[1]));
}

__device__ __forceinline__ uint4 pack_f8_to_h8(float4 v0, float4 v1) {
    __half2 h0 = __floats2half2_rn(v0.x, v0.y);
    __half2 h1 = __floats2half2_rn(v0.z, v0.w);
    __half2 h2 = __floats2half2_rn(v1.x, v1.y);
    __half2 h3 = __floats2half2_rn(v1.z, v1.w);
    uint4 u;
    u.x = *(unsigned*)&h0; u.y = *(unsigned*)&h1;
    u.z = *(unsigned*)&h2; u.w = *(unsigned*)&h3;
    return u;
}

// ---------------- layer-1 GEMM: C[M,256] = A_fp32[M,128] @ Bt[256,128]^T + bias ----------------
// BM=128, full N=256, BK=32, 512 threads (16 warps, 4M x 4N), warp tile 32x64.
// Register double-buffered global loads; A converted fp32->fp16 during smem staging.
__global__ __launch_bounds__(512) void gemm_f16_l1(
    const float* __restrict__ A, const __half* __restrict__ Bt,
    const float* __restrict__ bias, void* __restrict__ Cout,
    int M, int out_half)
{
    __shared__ __half As[128][40];
    __shared__ __half Bs[256][40];
    const int K = 128;
    int tid = threadIdx.x;
    int lane = tid & 31, warp = tid >> 5;
    int wm = warp & 3, wn = warp >> 2;
    int g = lane >> 2, t = lane & 3;
    int bm = blockIdx.x * 128;

    int arow = tid >> 2, aseg = (tid & 3) * 8;
    int brow0 = tid >> 2, brow1 = (tid + 512) >> 2;

    float acc[2][8][4];
    #pragma unroll
    for (int mi = 0; mi < 2; mi++)
        #pragma unroll
        for (int ni = 0; ni < 8; ni++)
            #pragma unroll
            for (int j = 0; j < 4; j++) acc[mi][ni][j] = 0.f;

    // prologue loads (k0 = 0)
    float4 va0 = make_float4(0.f, 0.f, 0.f, 0.f), va1 = va0;
    uint4 vb0, vb1;
    {
        int gr = bm + arow;
        if (gr < M) {
            const float* ap = A + (size_t)gr * K + aseg;
            va0 = *(const float4*)ap;
            va1 = *(const float4*)(ap + 4);
        }
        vb0 = *(const uint4*)(Bt + (size_t)brow0 * K + aseg);
        vb1 = *(const uint4*)(Bt + (size_t)brow1 * K + aseg);
    }

    for (int k0 = 0; k0 < K; k0 += 32) {
        *(uint4*)&As[arow][aseg] = pack_f8_to_h8(va0, va1);
        *(uint4*)&Bs[brow0][aseg] = vb0;
        *(uint4*)&Bs[brow1][aseg] = vb1;
        __syncthreads();

        if (k0 + 32 < K) {   // prefetch next tiles while computing current
            int gr = bm + arow;
            va0 = make_float4(0.f, 0.f, 0.f, 0.f); va1 = va0;
            if (gr < M) {
                const float* ap = A + (size_t)gr * K + k0 + 32 + aseg;
                va0 = *(const float4*)ap;
                va1 = *(const float4*)(ap + 4);
            }
            vb0 = *(const uint4*)(Bt + (size_t)brow0 * K + k0 + 32 + aseg);
            vb1 = *(const uint4*)(Bt + (size_t)brow1 * K + k0 + 32 + aseg);
        }

        #pragma unroll
        for (int kk = 0; kk < 32; kk += 16) {
            unsigned af[2][4], bf[8][2];
            #pragma unroll
            for (int mi = 0; mi < 2; mi++) {
                int m0 = wm * 32 + mi * 16;
                af[mi][0] = *(const unsigned*)&As[m0 + g    ][kk + 2 * t];
                af[mi][1] = *(const unsigned*)&As[m0 + g + 8][kk + 2 * t];
                af[mi][2] = *(const unsigned*)&As[m0 + g    ][kk + 2 * t + 8];
                af[mi][3] = *(const unsigned*)&As[m0 + g + 8][kk + 2 * t + 8];
            }
            #pragma unroll
            for (int ni = 0; ni < 8; ni++) {
                int n0 = wn * 64 + ni * 8;
                bf[ni][0] = *(const unsigned*)&Bs[n0 + g][kk + 2 * t];
                bf[ni][1] = *(const unsigned*)&Bs[n0 + g][kk + 2 * t + 8];
            }
            #pragma unroll
            for (int mi = 0; mi < 2; mi++)
                #pragma unroll
                for (int ni = 0; ni < 8; ni++)
                    mma_f16(acc[mi][ni], af[mi], bf[ni]);
        }
        __syncthreads();
    }

    #pragma unroll
    for (int mi = 0; mi < 2; mi++) {
        #pragma unroll
        for (int ni = 0; ni < 8; ni++) {
            int col = wn * 64 + ni * 8 + 2 * t;
            float2 bb = *(const float2*)(bias + col);
            int r0 = bm + wm * 32 + mi * 16 + g;
            int r1 = r0 + 8;
            if (out_half) {
                __half* C = (__half*)Cout;
                if (r0 < M)
                    *(__half2*)(C + (size_t)r0 * 256 + col) =
                        __floats2half2_rn(acc[mi][ni][0] + bb.x, acc[mi][ni][1] + bb.y);
                if (r1 < M)
                    *(__half2*)(C + (size_t)r1 * 256 + col) =
                        __floats2half2_rn(acc[mi][ni][2] + bb.x, acc[mi][ni][3] + bb.y);
            } else {
                float* C = (float*)Cout;
                if (r0 < M)
                    *(float2*)(C + (size_t)r0 * 256 + col) =
                        make_float2(acc[mi][ni][0] + bb.x, acc[mi][ni][1] + bb.y);
                if (r1 < M)
                    *(float2*)(C + (size_t)r1 * 256 + col) =
                        make_float2(acc[mi][ni][2] + bb.x, acc[mi][ni][3] + bb.y);
            }
        }
    }
}

// ---------------- layer-2 GEMM: C[M,64] = relu(bn(A[M,256])) @ Bt[64,256]^T + bias ----------------
__global__ __launch_bounds__(256) void gemm_f16_l2(
    const float* __restrict__ A, const __half* __restrict__ Bt,
    const float* __restrict__ bias, float* __restrict__ C, int M)
{
    __shared__ __half As[128][40];
    __shared__ __half Bs[64][40];
    const int K = 256;
    int tid = threadIdx.x;
    int lane = tid & 31, warp = tid >> 5;
    int wm = warp & 3, wn = warp >> 2;
    int g = lane >> 2, t = lane & 3;
    int bm = blockIdx.x * 128;

    float acc[2][4][4];
    #pragma unroll
    for (int mi = 0; mi < 2; mi++)
        #pragma unroll
        for (int ni = 0; ni < 4; ni++)
            #pragma unroll
            for (int j = 0; j < 4; j++) acc[mi][ni][j] = 0.f;

    for (int k0 = 0; k0 < K; k0 += 32) {
        int colA = (tid & 7) * 4;
        float4 sc = *(const float4*)(g_bn_scale + k0 + colA);
        float4 sh = *(const float4*)(g_bn_shift + k0 + colA);
        #pragma unroll
        for (int p = 0; p < 4; p++) {   // A tile 128x32 fp32 -> BN+ReLU -> fp16
            int row = (tid >> 3) + p * 32;
            int gr = bm + row;
            float4 v = (gr < M) ? *(const float4*)(A + (size_t)gr * K + k0 + colA)
                                : make_float4(0.f, 0.f, 0.f, 0.f);
            v.x = fmaxf(v.x * sc.x + sh.x, 0.f);
            v.y = fmaxf(v.y * sc.y + sh.y, 0.f);
            v.z = fmaxf(v.z * sc.z + sh.z, 0.f);
            v.w = fmaxf(v.w * sc.w + sh.w, 0.f);
            *(__half2*)&As[row][colA]     = __floats2half2_rn(v.x, v.y);
            *(__half2*)&As[row][colA + 2] = __floats2half2_rn(v.z, v.w);
        }
        {   // B tile 64x32 halves
            int row = tid >> 2, seg = (tid & 3) * 8;
            *(uint4*)&Bs[row][seg] = *(const uint4*)(Bt + (size_t)row * K + k0 + seg);
        }
        __syncthreads();
        #pragma unroll
        for (int kk = 0; kk < 32; kk += 16) {
            unsigned af[2][4], bf[4][2];
            #pragma unroll
            for (int mi = 0; mi < 2; mi++) {
                int m0 = wm * 32 + mi * 16;
                af[mi][0] = *(const unsigned*)&As[m0 + g    ][kk + 2 * t];
                af[mi][1] = *(const unsigned*)&As[m0 + g + 8][kk + 2 * t];
                af[mi][2] = *(const unsigned*)&As[m0 + g    ][kk + 2 * t + 8];
                af[mi][3] = *(const unsigned*)&As[m0 + g + 8][kk + 2 * t + 8];
            }
            #pragma unroll
            for (int ni = 0; ni < 4; ni++) {
                int n0 = wn * 32 + ni * 8;
                bf[ni][0] = *(const unsigned*)&Bs[n0 + g][kk + 2 * t];
                bf[ni][1] = *(const unsigned*)&Bs[n0 + g][kk + 2 * t + 8];
            }
            #pragma unroll
            for (int mi = 0; mi < 2; mi++)
                #pragma unroll
                for (int ni = 0; ni < 4; ni++)
                    mma_f16(acc[mi][ni], af[mi], bf[ni]);
        }
        __syncthreads();
    }

    #pragma unroll
    for (int mi = 0; mi < 2; mi++) {
        #pragma unroll
        for (int ni = 0; ni < 4; ni++) {
            int col = wn * 32 + ni * 8 + 2 * t;
            float2 bb = *(const float2*)(bias + col);
            int r0 = bm + wm * 32 + mi * 16 + g;
            int r1 = r0 + 8;
            if (r0 < M)
                *(float2*)(C + (size_t)r0 * 64 + col) =
                    make_float2(acc[mi][ni][0] + bb.x, acc[mi][ni][1] + bb.y);
            if (r1 < M)
                *(float2*)(C + (size_t)r1 * 64 + col) =
                    make_float2(acc[mi][ni][2] + bb.x, acc[mi][ni][3] + bb.y);
        }
    }
}

// ---------------- layer-1 fused edge kernel: 8-edge gather groups, online softmax ----------------
__global__ __launch_bounds__(256) void edge1_kernel(const float* __restrict__ att,
                                                    const float* __restrict__ bias)
{
    int w = (blockIdx.x * 256 + threadIdx.x) >> 5;
    int lane = threadIdx.x & 31;
    if (w >= N2) return;
    int off = lane * 8;

    float xr[8], at[8];
    {
        const float* xrp = g_xr1 + (size_t)w * D1 + off;
        float4 a = *(const float4*)xrp, b = *(const float4*)(xrp + 4);
        xr[0] = a.x; xr[1] = a.y; xr[2] = a.z; xr[3] = a.w;
        xr[4] = b.x; xr[5] = b.y; xr[6] = b.z; xr[7] = b.w;
        float4 c = *(const float4*)(att + off), d = *(const float4*)(att + off + 4);
        at[0] = c.x; at[1] = c.y; at[2] = c.z; at[3] = c.w;
        at[4] = d.x; at[5] = d.y; at[6] = d.z; at[7] = d.w;
    }

    float m = -INFINITY, s = 0.f;
    float ac[8] = {0.f, 0.f, 0.f, 0.f, 0.f, 0.f, 0.f, 0.f};

    int jb = g_rp1[w], je = g_rp1[w + 1];
    int j = jb;

    // 8-edge groups (MLP 8)
    for (; j + 8 <= je; j += 8) {
        uint4 rr[8];
        #pragma unroll
        for (int q = 0; q < 8; q++) {
            int src = __ldg(g_csr1 + j + q);
            rr[q] = __ldg((const uint4*)(g_xl1h + (size_t)src * D1 + off));
        }
        float p[8];
        #pragma unroll
        for (int q = 0; q < 8; q++) {
            float f[8]; unpack8(rr[q], f);
            float pp = 0.f;
            #pragma unroll
            for (int c = 0; c < 8; c++) pp += lrelu(f[c] + xr[c]) * at[c];
            pp += __shfl_xor_sync(FULLM, pp, 1);
            pp += __shfl_xor_sync(FULLM, pp, 2);
            pp += __shfl_xor_sync(FULLM, pp, 4);
            p[q] = pp;
        }
        float nm = m;
        #pragma unroll
        for (int q = 0; q < 8; q++) nm = fmaxf(nm, p[q]);
        float sc = __expf(m - nm);
        float wq[8], ssum = 0.f;
        #pragma unroll
        for (int q = 0; q < 8; q++) { wq[q] = __expf(p[q] - nm); ssum += wq[q]; }
        s = s * sc + ssum;
        #pragma unroll
        for (int c = 0; c < 8; c++) ac[c] *= sc;
        #pragma unroll
        for (int q = 0; q < 8; q++) {
            float f[8]; unpack8(rr[q], f);
            #pragma unroll
            for (int c = 0; c < 8; c++) ac[c] += wq[q] * f[c];
        }
        m = nm;
    }

    // 4-edge group
    for (; j + 4 <= je; j += 4) {
        uint4 rr[4];
        #pragma unroll
        for (int q = 0; q < 4; q++) {
            int src = __ldg(g_csr1 + j + q);
            rr[q] = __ldg((const uint4*)(g_xl1h + (size_t)src * D1 + off));
        }
        float p[4];
        #pragma unroll
        for (int q = 0; q < 4; q++) {
            float f[8]; unpack8(rr[q], f);
            float pp = 0.f;
            #pragma unroll
            for (int c = 0; c < 8; c++) pp += lrelu(f[c] + xr[c]) * at[c];
            pp += __shfl_xor_sync(FULLM, pp, 1);
            pp += __shfl_xor_sync(FULLM, pp, 2);
            pp += __shfl_xor_sync(FULLM, pp, 4);
            p[q] = pp;
        }
        float nm = fmaxf(fmaxf(fmaxf(p[0], p[1]), fmaxf(p[2], p[3])), m);
        float sc = __expf(m - nm);
        float wq[4], ssum = 0.f;
        #pragma unroll
        for (int q = 0; q < 4; q++) { wq[q] = __expf(p[q] - nm); ssum += wq[q]; }
        s = s * sc + ssum;
        #pragma unroll
        for (int c = 0; c < 8; c++) ac[c] *= sc;
        #pragma unroll
        for (int q = 0; q < 4; q++) {
            float f[8]; unpack8(rr[q], f);
            #pragma unroll
            for (int c = 0; c < 8; c++) ac[c] += wq[q] * f[c];
        }
        m = nm;
    }

    // scalar tail
    for (; j < je; ++j) {
        int src = __ldg(g_csr1 + j);
        uint4 raw = __ldg((const uint4*)(g_xl1h + (size_t)src * D1 + off));
        float f[8]; unpack8(raw, f);
        float pp = 0.f;
        #pragma unroll
        for (int c = 0; c < 8; c++) pp += lrelu(f[c] + xr[c]) * at[c];
        pp += __shfl_xor_sync(FULLM, pp, 1);
        pp += __shfl_xor_sync(FULLM, pp, 2);
        pp += __shfl_xor_sync(FULLM, pp, 4);
        float nm = fmaxf(m, pp);
        float sc = __expf(m - nm);
        float wg = __expf(pp - nm);
        s = s * sc + wg;
        #pragma unroll
        for (int c = 0; c < 8; c++) ac[c] = ac[c] * sc + wg * f[c];
        m = nm;
    }

    float inv = 1.f / (s + SM_EPS);
    float4 bA = *(const float4*)(bias + off);
    float4 bB = *(const float4*)(bias + off + 4);
    float4 o0 = make_float4(ac[0] * inv + bA.x, ac[1] * inv + bA.y,
                            ac[2] * inv + bA.z, ac[3] * inv + bA.w);
    float4 o1 = make_float4(ac[4] * inv + bB.x, ac[5] * inv + bB.y,
                            ac[6] * inv + bB.z, ac[7] * inv + bB.w);
    float* hp = g_h + (size_t)w * D1 + off;
    *(float4*)hp = o0;
    *(float4*)(hp + 4) = o1;
}

// ---------------- batchnorm statistics (single pass) ----------------
__global__ void bn_stats_kernel() {
    int col = threadIdx.x;
    float s = 0.f, q = 0.f;
    for (int r = blockIdx.x; r < N2; r += gridDim.x) {
        float v = g_h[(size_t)r * D1 + col];
        s += v;
        q += v * v;
    }
    atomicAdd(&g_bn_sum[col], s);
    atomicAdd(&g_bn_sqs[col], q);
}
__global__ void bn_final_kernel(const float* __restrict__ gamma, const float* __restrict__ beta) {
    int c = threadIdx.x;
    float mu = g_bn_sum[c] * (1.f / N2);
    float var = g_bn_sqs[c] * (1.f / N2) - mu * mu;
    var = fmaxf(var, 0.f);
    float sc = gamma[c] * rsqrtf(var + BN_EPS);
    g_bn_scale[c] = sc;
    g_bn_shift[c] = beta[c] - mu * sc;
}

// ---------------- layer-2 fused edge kernel + log_softmax ----------------
__global__ __launch_bounds__(256) void edge2_kernel(const float* __restrict__ att,
                                                    const float* __restrict__ bias,
                                                    float* __restrict__ out)
{
    int w = (blockIdx.x * 256 + threadIdx.x) >> 5;
    int lane = threadIdx.x & 31;
    if (w >= N3) return;
    int off = lane * 2;

    float2 xr = *(const float2*)(g_xr2 + (size_t)w * D2 + off);
    float2 at = *(const float2*)(att + off);
    float m = -INFINITY, s = 0.f, a0 = 0.f, a1 = 0.f;

    int jb = g_rp2[w], je = g_rp2[w + 1];
    for (int j = jb; j < je; ++j) {
        int src = g_csr2[j];
        float2 xj = *(const float2*)(g_xl2 + (size_t)src * D2 + off);
        float p = lrelu(xj.x + xr.x) * at.x + lrelu(xj.y + xr.y) * at.y;
        #pragma unroll
        for (int o = 16; o > 0; o >>= 1) p += __shfl_xor_sync(FULLM, p, o);
        float nm = fmaxf(m, p);
        float sc = __expf(m - nm);
        float wg = __expf(p - nm);
        s = s * sc + wg;
        a0 = a0 * sc + wg * xj.x;
        a1 = a1 * sc + wg * xj.y;
        m = nm;
    }
    float inv = 1.f / (s + SM_EPS);
    float o0 = a0 * inv + bias[off];
    float o1 = a1 * inv + bias[off + 1];

    float mx = fmaxf(o0, o1);
    #pragma unroll
    for (int o = 16; o > 0; o >>= 1) mx = fmaxf(mx, __shfl_xor_sync(FULLM, mx, o));
    float se = __expf(o0 - mx) + __expf(o1 - mx);
    #pragma unroll
    for (int o = 16; o > 0; o >>= 1) se += __shfl_xor_sync(FULLM, se, o);
    float lse = __logf(se);
    float2 r = make_float2(o0 - mx - lse, o1 - mx - lse);
    *(float2*)(out + (size_t)w * D2 + off) = r;
}

// ---------------- launch ----------------
extern "C" void kernel_launch(void* const* d_in, const int* in_sizes, int n_in,
                              void* d_out, int out_size)
{
    const float* x       = (const float*)d_in[0];
    const int*   ei1_src = (const int*)d_in[1];
    const int*   ei1_dst = (const int*)d_in[2];
    const int*   ei2_src = (const int*)d_in[3];
    const int*   ei2_dst = (const int*)d_in[4];
    const float* W1l     = (const float*)d_in[5];
    const float* b1l     = (const float*)d_in[6];
    const float* W1r     = (const float*)d_in[7];
    const float* b1r     = (const float*)d_in[8];
    const float* att1    = (const float*)d_in[9];
    const float* bias1   = (const float*)d_in[10];
    const float* gamma   = (const float*)d_in[11];
    const float* beta    = (const float*)d_in[12];
    const float* W2l     = (const float*)d_in[13];
    const float* b2l     = (const float*)d_in[14];
    const float* W2r     = (const float*)d_in[15];
    const float* b2r     = (const float*)d_in[16];
    const float* att2    = (const float*)d_in[17];
    const float* bias2   = (const float*)d_in[18];
    float* out = (float*)d_out;

    __half *p_xl1h, *p_w1lt, *p_w1rt, *p_w2lt, *p_w2rt;
    float *p_xr1, *p_h, *p_xl2, *p_xr2;
    cudaGetSymbolAddress((void**)&p_xl1h, g_xl1h);
    cudaGetSymbolAddress((void**)&p_w1lt, g_w1lt);
    cudaGetSymbolAddress((void**)&p_w1rt, g_w1rt);
    cudaGetSymbolAddress((void**)&p_w2lt, g_w2lt);
    cudaGetSymbolAddress((void**)&p_w2rt, g_w2rt);
    cudaGetSymbolAddress((void**)&p_xr1, g_xr1);
    cudaGetSymbolAddress((void**)&p_h,   g_h);
    cudaGetSymbolAddress((void**)&p_xl2, g_xl2);
    cudaGetSymbolAddress((void**)&p_xr2, g_xr2);

    // CSR build
    zero_kernel<<<(N2 + 255) / 256, 256>>>();
    hist_kernel<<<(E1 / 4 + 255) / 256, 256>>>(ei1_dst, ei2_dst);
    scan2_kernel<<<2, 1024>>>();
    scatter_kernel<<<(E1 / 4 + 255) / 256, 256>>>(ei1_src, ei1_dst, ei2_src, ei2_dst);

    // weight prep
    cvt_w_kernel<<<(128 * 256 + 255) / 256, 256>>>(W1l, W1r, W2l, W2r);

    // layer 1 projections (fp16 mma, double-buffered)
    gemm_f16_l1<<<N1 / 128, 512>>>(x, p_w1lt, b1l, p_xl1h, N1, 1);
    gemm_f16_l1<<<(N2 + 127) / 128, 512>>>(x, p_w1rt, b1r, p_xr1, N2, 0);

    // layer 1 attention + aggregation
    edge1_kernel<<<(N2 * 32 + 255) / 256, 256>>>(att1, bias1);

    // batchnorm stats (apply fused into layer-2 GEMM A loads)
    bn_stats_kernel<<<256, 256>>>();
    bn_final_kernel<<<1, 256>>>(gamma, beta);

    // layer 2 projections (BN+ReLU fused, fp16 mma)
    gemm_f16_l2<<<(N2 + 127) / 128, 256>>>(p_h, p_w2lt, b2l, p_xl2, N2);
    gemm_f16_l2<<<(N3 + 127) / 128, 256>>>(p_h, p_w2rt, b2r, p_xr2, N3);

    // layer 2 attention + aggregation + log_softmax
    edge2_kernel<<<(N3 * 32 + 255) / 256, 256>>>(att2, bias2, out);
}

// round 9
// speedup vs baseline: 2.1421x; 1.1055x over previous
#include <cuda_runtime.h>
#include <cuda_bf16.h>
#include <cuda_fp16.h>
#include <math.h>

// ---------------- problem constants ----------------
#define N1 160000
#define N2 40000
#define N3 10000
#define E1 800000
#define E2 200000
#define D1 256          // H1*HID
#define D2 64           // OUT
#define NEG_SLOPE 0.2f
#define BN_EPS 1e-5f
#define SM_EPS 1e-16f
#define FULLM 0xFFFFFFFFu

// ---------------- device scratch (allocation-free) ----------------
__device__ __half g_xl1h[(size_t)N1 * D1];   // 82 MB  fp16 gather table
__device__ float  g_xr1[(size_t)N2 * D1];    // 41 MB
__device__ float  g_h  [(size_t)N2 * D1];    // 41 MB  (layer1 out, pre-BN)
__device__ float  g_xl2[(size_t)N2 * D2];    // 10.2 MB
__device__ float  g_xr2[(size_t)N3 * D2];    // 2.6 MB

__device__ __half g_w1lt[D1 * 128];          // [N=256][K=128]
__device__ __half g_w1rt[D1 * 128];
__device__ __half g_w2lt[D2 * D1];           // [N=64][K=256]
__device__ __half g_w2rt[D2 * D1];

__device__ int g_cnt1[N2];
__device__ int g_rp1 [N2 + 1];
__device__ int g_cur1[N2];
__device__ int g_csr1[E1];

__device__ int g_cnt2[N3];
__device__ int g_rp2 [N3 + 1];
__device__ int g_cur2[N3];
__device__ int g_csr2[E2];

__device__ float g_bn_sum[D1];
__device__ float g_bn_sqs[D1];
__device__ float g_bn_scale[D1];
__device__ float g_bn_shift[D1];

__device__ __forceinline__ float lrelu(float v) { return v > 0.f ? v : NEG_SLOPE * v; }

__device__ __forceinline__ void unpack8(uint4 r, float* f) {
    float2 a = __half22float2(*reinterpret_cast<const __half2*>(&r.x));
    float2 b = __half22float2(*reinterpret_cast<const __half2*>(&r.y));
    float2 c = __half22float2(*reinterpret_cast<const __half2*>(&r.z));
    float2 d = __half22float2(*reinterpret_cast<const __half2*>(&r.w));
    f[0] = a.x; f[1] = a.y; f[2] = b.x; f[3] = b.y;
    f[4] = c.x; f[5] = c.y; f[6] = d.x; f[7] = d.y;
}

// ---------------- CSR build ----------------
__global__ void zero_kernel() {
    int i = blockIdx.x * blockDim.x + threadIdx.x;
    if (i < N2) g_cnt1[i] = 0;
    if (i < N3) g_cnt2[i] = 0;
    if (i < D1) { g_bn_sum[i] = 0.f; g_bn_sqs[i] = 0.f; }
}

// 4 edges per thread (E1, E2 divisible by 4)
__global__ void hist_kernel(const int* __restrict__ d1, const int* __restrict__ d2) {
    int i = (blockIdx.x * blockDim.x + threadIdx.x) * 4;
    if (i < E1) {
        int4 v = *(const int4*)(d1 + i);
        atomicAdd(&g_cnt1[v.x], 1); atomicAdd(&g_cnt1[v.y], 1);
        atomicAdd(&g_cnt1[v.z], 1); atomicAdd(&g_cnt1[v.w], 1);
    }
    if (i < E2) {
        int4 v = *(const int4*)(d2 + i);
        atomicAdd(&g_cnt2[v.x], 1); atomicAdd(&g_cnt2[v.y], 1);
        atomicAdd(&g_cnt2[v.z], 1); atomicAdd(&g_cnt2[v.w], 1);
    }
}

// 2-block warp-shuffle exclusive scan: blockIdx 0 -> layer1 (N2), 1 -> layer2 (N3)
__global__ __launch_bounds__(1024) void scan2_kernel() {
    int which = blockIdx.x;
    const int* cnt = which ? g_cnt2 : g_cnt1;
    int* rp  = which ? g_rp2  : g_rp1;
    int* cur = which ? g_cur2 : g_cur1;
    int n    = which ? N3     : N2;

    __shared__ int wsum[32];
    __shared__ int carry;
    int tid = threadIdx.x;
    int lane = tid & 31, wid = tid >> 5;
    if (tid == 0) carry = 0;
    __syncthreads();

    for (int base = 0; base < n; base += 4096) {
        int i0 = base + tid * 4;
        int v0 = (i0 + 0 < n) ? cnt[i0 + 0] : 0;
        int v1 = (i0 + 1 < n) ? cnt[i0 + 1] : 0;
        int v2 = (i0 + 2 < n) ? cnt[i0 + 2] : 0;
        int v3 = (i0 + 3 < n) ? cnt[i0 + 3] : 0;
        int tot = v0 + v1 + v2 + v3;
        int isum = tot;
        #pragma unroll
        for (int off = 1; off < 32; off <<= 1) {
            int t = __shfl_up_sync(FULLM, isum, off);
            if (lane >= off) isum += t;
        }
        if (lane == 31) wsum[wid] = isum;
        __syncthreads();
        if (wid == 0) {
            int s = wsum[lane];
            #pragma unroll
            for (int off = 1; off < 32; off <<= 1) {
                int t = __shfl_up_sync(FULLM, s, off);
                if (lane >= off) s += t;
            }
            wsum[lane] = s;
        }
        __syncthreads();
        int carryv = carry;
        int woff = (wid > 0) ? wsum[wid - 1] : 0;
        int excl = carryv + woff + (isum - tot);
        if (i0 + 0 < n) { rp[i0 + 0] = excl;                cur[i0 + 0] = excl; }
        if (i0 + 1 < n) { rp[i0 + 1] = excl + v0;           cur[i0 + 1] = excl + v0; }
        if (i0 + 2 < n) { rp[i0 + 2] = excl + v0 + v1;      cur[i0 + 2] = excl + v0 + v1; }
        if (i0 + 3 < n) { rp[i0 + 3] = excl + v0 + v1 + v2; cur[i0 + 3] = excl + v0 + v1 + v2; }
        __syncthreads();
        if (tid == 0) carry = carryv + wsum[31];
        __syncthreads();
    }
    if (tid == 0) rp[n] = carry;
}

// merged + vectorized scatter (4 edges/thread)
__global__ void scatter_kernel(const int* __restrict__ src1, const int* __restrict__ dst1,
                               const int* __restrict__ src2, const int* __restrict__ dst2) {
    int e = (blockIdx.x * blockDim.x + threadIdx.x) * 4;
    if (e < E1) {
        int4 s = *(const int4*)(src1 + e);
        int4 d = *(const int4*)(dst1 + e);
        int p;
        p = atomicAdd(&g_cur1[d.x], 1); g_csr1[p] = s.x;
        p = atomicAdd(&g_cur1[d.y], 1); g_csr1[p] = s.y;
        p = atomicAdd(&g_cur1[d.z], 1); g_csr1[p] = s.z;
        p = atomicAdd(&g_cur1[d.w], 1); g_csr1[p] = s.w;
    }
    if (e < E2) {
        int4 s = *(const int4*)(src2 + e);
        int4 d = *(const int4*)(dst2 + e);
        int p;
        p = atomicAdd(&g_cur2[d.x], 1); g_csr2[p] = s.x;
        p = atomicAdd(&g_cur2[d.y], 1); g_csr2[p] = s.y;
        p = atomicAdd(&g_cur2[d.z], 1); g_csr2[p] = s.z;
        p = atomicAdd(&g_cur2[d.w], 1); g_csr2[p] = s.w;
    }
}

// transpose weights to [N][K] fp16
__global__ void cvt_w_kernel(const float* __restrict__ W1l, const float* __restrict__ W1r,
                             const float* __restrict__ W2l, const float* __restrict__ W2r) {
    int i = blockIdx.x * blockDim.x + threadIdx.x;
    if (i < 128 * 256) {                  // W1: [K=128][N=256]
        int k = i >> 8, n = i & 255;
        g_w1lt[n * 128 + k] = __float2half(W1l[i]);
        g_w1rt[n * 128 + k] = __float2half(W1r[i]);
    }
    if (i < 256 * 64) {                   // W2: [K=256][N=64]
        int k = i >> 6, n = i & 63;
        g_w2lt[n * 256 + k] = __float2half(W2l[i]);
        g_w2rt[n * 256 + k] = __float2half(W2r[i]);
    }
}

// ---------------- fp16 mma helper ----------------
__device__ __forceinline__ void mma_f16(float* d, const unsigned* a, const unsigned* b) {
    asm volatile("mma.sync.aligned.m16n8k16.row.col.f32.f16.f16.f32 "
        "{%0,%1,%2,%3}, {%4,%5,%6,%7}, {%8,%9}, {%0,%1,%2,%3};"
        : "+f"(d[0]), "+f"(d[1]), "+f"(d[2]), "+f"(d[3])
        : "r"(a[0]), "r"(a[1]), "r"(a[2]), "r"(a[3]), "r"(b[0]), "r"(b[1]));
}

__device__ __forceinline__ uint4 pack_f8_to_h8(float4 v0, float4 v1) {
    __half2 h0 = __floats2half2_rn(v0.x, v0.y);
    __half2 h1 = __floats2half2_rn(v0.z, v0.w);
    __half2 h2 = __floats2half2_rn(v1.x, v1.y);
    __half2 h3 = __floats2half2_rn(v1.z, v1.w);
    uint4 u;
    u.x = *(unsigned*)&h0; u.y = *(unsigned*)&h1;
    u.z = *(unsigned*)&h2; u.w = *(unsigned*)&h3;
    return u;
}

// ---------------- layer-1 GEMM: C[M,256] = A_fp32[M,128] @ Bt[256,128]^T + bias ----------------
__global__ __launch_bounds__(512) void gemm_f16_l1(
    const float* __restrict__ A, const __half* __restrict__ Bt,
    const float* __restrict__ bias, void* __restrict__ Cout,
    int M, int out_half)
{
    __shared__ __half As[128][40];
    __shared__ __half Bs[256][40];
    const int K = 128;
    int tid = threadIdx.x;
    int lane = tid & 31, warp = tid >> 5;
    int wm = warp & 3, wn = warp >> 2;
    int g = lane >> 2, t = lane & 3;
    int bm = blockIdx.x * 128;

    int arow = tid >> 2, aseg = (tid & 3) * 8;
    int brow0 = tid >> 2, brow1 = (tid + 512) >> 2;

    float acc[2][8][4];
    #pragma unroll
    for (int mi = 0; mi < 2; mi++)
        #pragma unroll
        for (int ni = 0; ni < 8; ni++)
            #pragma unroll
            for (int j = 0; j < 4; j++) acc[mi][ni][j] = 0.f;

    float4 va0 = make_float4(0.f, 0.f, 0.f, 0.f), va1 = va0;
    uint4 vb0, vb1;
    {
        int gr = bm + arow;
        if (gr < M) {
            const float* ap = A + (size_t)gr * K + aseg;
            va0 = *(const float4*)ap;
            va1 = *(const float4*)(ap + 4);
        }
        vb0 = *(const uint4*)(Bt + (size_t)brow0 * K + aseg);
        vb1 = *(const uint4*)(Bt + (size_t)brow1 * K + aseg);
    }

    for (int k0 = 0; k0 < K; k0 += 32) {
        *(uint4*)&As[arow][aseg] = pack_f8_to_h8(va0, va1);
        *(uint4*)&Bs[brow0][aseg] = vb0;
        *(uint4*)&Bs[brow1][aseg] = vb1;
        __syncthreads();

        if (k0 + 32 < K) {
            int gr = bm + arow;
            va0 = make_float4(0.f, 0.f, 0.f, 0.f); va1 = va0;
            if (gr < M) {
                const float* ap = A + (size_t)gr * K + k0 + 32 + aseg;
                va0 = *(const float4*)ap;
                va1 = *(const float4*)(ap + 4);
            }
            vb0 = *(const uint4*)(Bt + (size_t)brow0 * K + k0 + 32 + aseg);
            vb1 = *(const uint4*)(Bt + (size_t)brow1 * K + k0 + 32 + aseg);
        }

        #pragma unroll
        for (int kk = 0; kk < 32; kk += 16) {
            unsigned af[2][4], bf[8][2];
            #pragma unroll
            for (int mi = 0; mi < 2; mi++) {
                int m0 = wm * 32 + mi * 16;
                af[mi][0] = *(const unsigned*)&As[m0 + g    ][kk + 2 * t];
                af[mi][1] = *(const unsigned*)&As[m0 + g + 8][kk + 2 * t];
                af[mi][2] = *(const unsigned*)&As[m0 + g    ][kk + 2 * t + 8];
                af[mi][3] = *(const unsigned*)&As[m0 + g + 8][kk + 2 * t + 8];
            }
            #pragma unroll
            for (int ni = 0; ni < 8; ni++) {
                int n0 = wn * 64 + ni * 8;
                bf[ni][0] = *(const unsigned*)&Bs[n0 + g][kk + 2 * t];
                bf[ni][1] = *(const unsigned*)&Bs[n0 + g][kk + 2 * t + 8];
            }
            #pragma unroll
            for (int mi = 0; mi < 2; mi++)
                #pragma unroll
                for (int ni = 0; ni < 8; ni++)
                    mma_f16(acc[mi][ni], af[mi], bf[ni]);
        }
        __syncthreads();
    }

    #pragma unroll
    for (int mi = 0; mi < 2; mi++) {
        #pragma unroll
        for (int ni = 0; ni < 8; ni++) {
            int col = wn * 64 + ni * 8 + 2 * t;
            float2 bb = *(const float2*)(bias + col);
            int r0 = bm + wm * 32 + mi * 16 + g;
            int r1 = r0 + 8;
            if (out_half) {
                __half* C = (__half*)Cout;
                if (r0 < M)
                    *(__half2*)(C + (size_t)r0 * 256 + col) =
                        __floats2half2_rn(acc[mi][ni][0] + bb.x, acc[mi][ni][1] + bb.y);
                if (r1 < M)
                    *(__half2*)(C + (size_t)r1 * 256 + col) =
                        __floats2half2_rn(acc[mi][ni][2] + bb.x, acc[mi][ni][3] + bb.y);
            } else {
                float* C = (float*)Cout;
                if (r0 < M)
                    *(float2*)(C + (size_t)r0 * 256 + col) =
                        make_float2(acc[mi][ni][0] + bb.x, acc[mi][ni][1] + bb.y);
                if (r1 < M)
                    *(float2*)(C + (size_t)r1 * 256 + col) =
                        make_float2(acc[mi][ni][2] + bb.x, acc[mi][ni][3] + bb.y);
            }
        }
    }
}

// ---------------- layer-2 GEMM: C[M,64] = relu(bn(A[M,256])) @ Bt[64,256]^T + bias ----------------
__global__ __launch_bounds__(256) void gemm_f16_l2(
    const float* __restrict__ A, const __half* __restrict__ Bt,
    const float* __restrict__ bias, float* __restrict__ C, int M)
{
    __shared__ __half As[128][40];
    __shared__ __half Bs[64][40];
    const int K = 256;
    int tid = threadIdx.x;
    int lane = tid & 31, warp = tid >> 5;
    int wm = warp & 3, wn = warp >> 2;
    int g = lane >> 2, t = lane & 3;
    int bm = blockIdx.x * 128;

    float acc[2][4][4];
    #pragma unroll
    for (int mi = 0; mi < 2; mi++)
        #pragma unroll
        for (int ni = 0; ni < 4; ni++)
            #pragma unroll
            for (int j = 0; j < 4; j++) acc[mi][ni][j] = 0.f;

    for (int k0 = 0; k0 < K; k0 += 32) {
        int colA = (tid & 7) * 4;
        float4 sc = *(const float4*)(g_bn_scale + k0 + colA);
        float4 sh = *(const float4*)(g_bn_shift + k0 + colA);
        #pragma unroll
        for (int p = 0; p < 4; p++) {
            int row = (tid >> 3) + p * 32;
            int gr = bm + row;
            float4 v = (gr < M) ? *(const float4*)(A + (size_t)gr * K + k0 + colA)
                                : make_float4(0.f, 0.f, 0.f, 0.f);
            v.x = fmaxf(v.x * sc.x + sh.x, 0.f);
            v.y = fmaxf(v.y * sc.y + sh.y, 0.f);
            v.z = fmaxf(v.z * sc.z + sh.z, 0.f);
            v.w = fmaxf(v.w * sc.w + sh.w, 0.f);
            *(__half2*)&As[row][colA]     = __floats2half2_rn(v.x, v.y);
            *(__half2*)&As[row][colA + 2] = __floats2half2_rn(v.z, v.w);
        }
        {
            int row = tid >> 2, seg = (tid & 3) * 8;
            *(uint4*)&Bs[row][seg] = *(const uint4*)(Bt + (size_t)row * K + k0 + seg);
        }
        __syncthreads();
        #pragma unroll
        for (int kk = 0; kk < 32; kk += 16) {
            unsigned af[2][4], bf[4][2];
            #pragma unroll
            for (int mi = 0; mi < 2; mi++) {
                int m0 = wm * 32 + mi * 16;
                af[mi][0] = *(const unsigned*)&As[m0 + g    ][kk + 2 * t];
                af[mi][1] = *(const unsigned*)&As[m0 + g + 8][kk + 2 * t];
                af[mi][2] = *(const unsigned*)&As[m0 + g    ][kk + 2 * t + 8];
                af[mi][3] = *(const unsigned*)&As[m0 + g + 8][kk + 2 * t + 8];
            }
            #pragma unroll
            for (int ni = 0; ni < 4; ni++) {
                int n0 = wn * 32 + ni * 8;
                bf[ni][0] = *(const unsigned*)&Bs[n0 + g][kk + 2 * t];
                bf[ni][1] = *(const unsigned*)&Bs[n0 + g][kk + 2 * t + 8];
            }
            #pragma unroll
            for (int mi = 0; mi < 2; mi++)
                #pragma unroll
                for (int ni = 0; ni < 4; ni++)
                    mma_f16(acc[mi][ni], af[mi], bf[ni]);
        }
        __syncthreads();
    }

    #pragma unroll
    for (int mi = 0; mi < 2; mi++) {
        #pragma unroll
        for (int ni = 0; ni < 4; ni++) {
            int col = wn * 32 + ni * 8 + 2 * t;
            float2 bb = *(const float2*)(bias + col);
            int r0 = bm + wm * 32 + mi * 16 + g;
            int r1 = r0 + 8;
            if (r0 < M)
                *(float2*)(C + (size_t)r0 * 64 + col) =
                    make_float2(acc[mi][ni][0] + bb.x, acc[mi][ni][1] + bb.y);
            if (r1 < M)
                *(float2*)(C + (size_t)r1 * 64 + col) =
                    make_float2(acc[mi][ni][2] + bb.x, acc[mi][ni][3] + bb.y);
        }
    }
}

// ---------------- layer-1 fused edge kernel: 8-edge gather groups, online softmax ----------------
__global__ __launch_bounds__(256) void edge1_kernel(const float* __restrict__ att,
                                                    const float* __restrict__ bias)
{
    int w = (blockIdx.x * 256 + threadIdx.x) >> 5;
    int lane = threadIdx.x & 31;
    if (w >= N2) return;
    int off = lane * 8;

    float xr[8], at[8];
    {
        const float* xrp = g_xr1 + (size_t)w * D1 + off;
        float4 a = *(const float4*)xrp, b = *(const float4*)(xrp + 4);
        xr[0] = a.x; xr[1] = a.y; xr[2] = a.z; xr[3] = a.w;
        xr[4] = b.x; xr[5] = b.y; xr[6] = b.z; xr[7] = b.w;
        float4 c = *(const float4*)(att + off), d = *(const float4*)(att + off + 4);
        at[0] = c.x; at[1] = c.y; at[2] = c.z; at[3] = c.w;
        at[4] = d.x; at[5] = d.y; at[6] = d.z; at[7] = d.w;
    }

    float m = -INFINITY, s = 0.f;
    float ac[8] = {0.f, 0.f, 0.f, 0.f, 0.f, 0.f, 0.f, 0.f};

    int jb = g_rp1[w], je = g_rp1[w + 1];
    int j = jb;

    for (; j + 8 <= je; j += 8) {
        uint4 rr[8];
        #pragma unroll
        for (int q = 0; q < 8; q++) {
            int src = __ldg(g_csr1 + j + q);
            rr[q] = __ldg((const uint4*)(g_xl1h + (size_t)src * D1 + off));
        }
        float p[8];
        #pragma unroll
        for (int q = 0; q < 8; q++) {
            float f[8]; unpack8(rr[q], f);
            float pp = 0.f;
            #pragma unroll
            for (int c = 0; c < 8; c++) pp += lrelu(f[c] + xr[c]) * at[c];
            pp += __shfl_xor_sync(FULLM, pp, 1);
            pp += __shfl_xor_sync(FULLM, pp, 2);
            pp += __shfl_xor_sync(FULLM, pp, 4);
            p[q] = pp;
        }
        float nm = m;
        #pragma unroll
        for (int q = 0; q < 8; q++) nm = fmaxf(nm, p[q]);
        float sc = __expf(m - nm);
        float wq[8], ssum = 0.f;
        #pragma unroll
        for (int q = 0; q < 8; q++) { wq[q] = __expf(p[q] - nm); ssum += wq[q]; }
        s = s * sc + ssum;
        #pragma unroll
        for (int c = 0; c < 8; c++) ac[c] *= sc;
        #pragma unroll
        for (int q = 0; q < 8; q++) {
            float f[8]; unpack8(rr[q], f);
            #pragma unroll
            for (int c = 0; c < 8; c++) ac[c] += wq[q] * f[c];
        }
        m = nm;
    }

    for (; j + 4 <= je; j += 4) {
        uint4 rr[4];
        #pragma unroll
        for (int q = 0; q < 4; q++) {
            int src = __ldg(g_csr1 + j + q);
            rr[q] = __ldg((const uint4*)(g_xl1h + (size_t)src * D1 + off));
        }
        float p[4];
        #pragma unroll
        for (int q = 0; q < 4; q++) {
            float f[8]; unpack8(rr[q], f);
            float pp = 0.f;
            #pragma unroll
            for (int c = 0; c < 8; c++) pp += lrelu(f[c] + xr[c]) * at[c];
            pp += __shfl_xor_sync(FULLM, pp, 1);
            pp += __shfl_xor_sync(FULLM, pp, 2);
            pp += __shfl_xor_sync(FULLM, pp, 4);
            p[q] = pp;
        }
        float nm = fmaxf(fmaxf(fmaxf(p[0], p[1]), fmaxf(p[2], p[3])), m);
        float sc = __expf(m - nm);
        float wq[4], ssum = 0.f;
        #pragma unroll
        for (int q = 0; q < 4; q++) { wq[q] = __expf(p[q] - nm); ssum += wq[q]; }
        s = s * sc + ssum;
        #pragma unroll
        for (int c = 0; c < 8; c++) ac[c] *= sc;
        #pragma unroll
        for (int q = 0; q < 4; q++) {
            float f[8]; unpack8(rr[q], f);
            #pragma unroll
            for (int c = 0; c < 8; c++) ac[c] += wq[q] * f[c];
        }
        m = nm;
    }

    for (; j < je; ++j) {
        int src = __ldg(g_csr1 + j);
        uint4 raw = __ldg((const uint4*)(g_xl1h + (size_t)src * D1 + off));
        float f[8]; unpack8(raw, f);
        float pp = 0.f;
        #pragma unroll
        for (int c = 0; c < 8; c++) pp += lrelu(f[c] + xr[c]) * at[c];
        pp += __shfl_xor_sync(FULLM, pp, 1);
        pp += __shfl_xor_sync(FULLM, pp, 2);
        pp += __shfl_xor_sync(FULLM, pp, 4);
        float nm = fmaxf(m, pp);
        float sc = __expf(m - nm);
        float wg = __expf(pp - nm);
        s = s * sc + wg;
        #pragma unroll
        for (int c = 0; c < 8; c++) ac[c] = ac[c] * sc + wg * f[c];
        m = nm;
    }

    float inv = 1.f / (s + SM_EPS);
    float4 bA = *(const float4*)(bias + off);
    float4 bB = *(const float4*)(bias + off + 4);
    float4 o0 = make_float4(ac[0] * inv + bA.x, ac[1] * inv + bA.y,
                            ac[2] * inv + bA.z, ac[3] * inv + bA.w);
    float4 o1 = make_float4(ac[4] * inv + bB.x, ac[5] * inv + bB.y,
                            ac[6] * inv + bB.z, ac[7] * inv + bB.w);
    float* hp = g_h + (size_t)w * D1 + off;
    *(float4*)hp = o0;
    *(float4*)(hp + 4) = o1;
}

// ---------------- batchnorm statistics (single pass) ----------------
__global__ void bn_stats_kernel() {
    int col = threadIdx.x;
    float s = 0.f, q = 0.f;
    for (int r = blockIdx.x; r < N2; r += gridDim.x) {
        float v = g_h[(size_t)r * D1 + col];
        s += v;
        q += v * v;
    }
    atomicAdd(&g_bn_sum[col], s);
    atomicAdd(&g_bn_sqs[col], q);
}
__global__ void bn_final_kernel(const float* __restrict__ gamma, const float* __restrict__ beta) {
    int c = threadIdx.x;
    float mu = g_bn_sum[c] * (1.f / N2);
    float var = g_bn_sqs[c] * (1.f / N2) - mu * mu;
    var = fmaxf(var, 0.f);
    float sc = gamma[c] * rsqrtf(var + BN_EPS);
    g_bn_scale[c] = sc;
    g_bn_shift[c] = beta[c] - mu * sc;
}

// ---------------- layer-2 fused edge kernel + log_softmax ----------------
__global__ __launch_bounds__(256) void edge2_kernel(const float* __restrict__ att,
                                                    const float* __restrict__ bias,
                                                    float* __restrict__ out)
{
    int w = (blockIdx.x * 256 + threadIdx.x) >> 5;
    int lane = threadIdx.x & 31;
    if (w >= N3) return;
    int off = lane * 2;

    float2 xr = *(const float2*)(g_xr2 + (size_t)w * D2 + off);
    float2 at = *(const float2*)(att + off);
    float m = -INFINITY, s = 0.f, a0 = 0.f, a1 = 0.f;

    int jb = g_rp2[w], je = g_rp2[w + 1];
    for (int j = jb; j < je; ++j) {
        int src = g_csr2[j];
        float2 xj = *(const float2*)(g_xl2 + (size_t)src * D2 + off);
        float p = lrelu(xj.x + xr.x) * at.x + lrelu(xj.y + xr.y) * at.y;
        #pragma unroll
        for (int o = 16; o > 0; o >>= 1) p += __shfl_xor_sync(FULLM, p, o);
        float nm = fmaxf(m, p);
        float sc = __expf(m - nm);
        float wg = __expf(p - nm);
        s = s * sc + wg;
        a0 = a0 * sc + wg * xj.x;
        a1 = a1 * sc + wg * xj.y;
        m = nm;
    }
    float inv = 1.f / (s + SM_EPS);
    float o0 = a0 * inv + bias[off];
    float o1 = a1 * inv + bias[off + 1];

    float mx = fmaxf(o0, o1);
    #pragma unroll
    for (int o = 16; o > 0; o >>= 1) mx = fmaxf(mx, __shfl_xor_sync(FULLM, mx, o));
    float se = __expf(o0 - mx) + __expf(o1 - mx);
    #pragma unroll
    for (int o = 16; o > 0; o >>= 1) se += __shfl_xor_sync(FULLM, se, o);
    float lse = __logf(se);
    float2 r = make_float2(o0 - mx - lse, o1 - mx - lse);
    *(float2*)(out + (size_t)w * D2 + off) = r;
}

// ---------------- launch ----------------
extern "C" void kernel_launch(void* const* d_in, const int* in_sizes, int n_in,
                              void* d_out, int out_size)
{
    const float* x       = (const float*)d_in[0];
    const int*   ei1_src = (const int*)d_in[1];
    const int*   ei1_dst = (const int*)d_in[2];
    const int*   ei2_src = (const int*)d_in[3];
    const int*   ei2_dst = (const int*)d_in[4];
    const float* W1l     = (const float*)d_in[5];
    const float* b1l     = (const float*)d_in[6];
    const float* W1r     = (const float*)d_in[7];
    const float* b1r     = (const float*)d_in[8];
    const float* att1    = (const float*)d_in[9];
    const float* bias1   = (const float*)d_in[10];
    const float* gamma   = (const float*)d_in[11];
    const float* beta    = (const float*)d_in[12];
    const float* W2l     = (const float*)d_in[13];
    const float* b2l     = (const float*)d_in[14];
    const float* W2r     = (const float*)d_in[15];
    const float* b2r     = (const float*)d_in[16];
    const float* att2    = (const float*)d_in[17];
    const float* bias2   = (const float*)d_in[18];
    float* out = (float*)d_out;

    __half *p_xl1h, *p_w1lt, *p_w1rt, *p_w2lt, *p_w2rt;
    float *p_xr1, *p_h, *p_xl2, *p_xr2;
    cudaGetSymbolAddress((void**)&p_xl1h, g_xl1h);
    cudaGetSymbolAddress((void**)&p_w1lt, g_w1lt);
    cudaGetSymbolAddress((void**)&p_w1rt, g_w1rt);
    cudaGetSymbolAddress((void**)&p_w2lt, g_w2lt);
    cudaGetSymbolAddress((void**)&p_w2rt, g_w2rt);
    cudaGetSymbolAddress((void**)&p_xr1, g_xr1);
    cudaGetSymbolAddress((void**)&p_h,   g_h);
    cudaGetSymbolAddress((void**)&p_xl2, g_xl2);
    cudaGetSymbolAddress((void**)&p_xr2, g_xr2);

    // fork side stream for the CSR chain (capturable event-fork pattern).
    // Objects intentionally not destroyed: kernel_launch is invoked only a
    // handful of times (correctness + capture); destroying a forked stream
    // mid-capture can invalidate the capture.
    cudaStream_t s2;
    cudaStreamCreateWithFlags(&s2, cudaStreamNonBlocking);
    cudaEvent_t evF, evJ;
    cudaEventCreateWithFlags(&evF, cudaEventDisableTiming);
    cudaEventCreateWithFlags(&evJ, cudaEventDisableTiming);

    cudaEventRecord(evF, 0);
    cudaStreamWaitEvent(s2, evF, 0);

    // CSR chain on s2 — overlaps with weight prep + layer-1 GEMMs below.
    // Submission order keeps gemm_f16_l1(N1) as the 4th kernel for ncu capture:
    //   1: zero(s2)  2: hist(s2)  3: cvt_w(main)  4: gemm_f16_l1(main)
    zero_kernel<<<(N2 + 255) / 256, 256, 0, s2>>>();
    hist_kernel<<<(E1 / 4 + 255) / 256, 256, 0, s2>>>(ei1_dst, ei2_dst);

    cvt_w_kernel<<<(128 * 256 + 255) / 256, 256>>>(W1l, W1r, W2l, W2r);
    gemm_f16_l1<<<N1 / 128, 512>>>(x, p_w1lt, b1l, p_xl1h, N1, 1);

    scan2_kernel<<<2, 1024, 0, s2>>>();
    scatter_kernel<<<(E1 / 4 + 255) / 256, 256, 0, s2>>>(ei1_src, ei1_dst, ei2_src, ei2_dst);
    cudaEventRecord(evJ, s2);

    gemm_f16_l1<<<(N2 + 127) / 128, 512>>>(x, p_w1rt, b1r, p_xr1, N2, 0);

    // join: edge1 needs both the CSR and the GEMM outputs
    cudaStreamWaitEvent(0, evJ, 0);

    edge1_kernel<<<(N2 * 32 + 255) / 256, 256>>>(att1, bias1);

    bn_stats_kernel<<<256, 256>>>();
    bn_final_kernel<<<1, 256>>>(gamma, beta);

    gemm_f16_l2<<<(N2 + 127) / 128, 256>>>(p_h, p_w2lt, b2l, p_xl2, N2);
    gemm_f16_l2<<<(N3 + 127) / 128, 256>>>(p_h, p_w2rt, b2r, p_xr2, N3);

    edge2_kernel<<<(N3 * 32 + 255) / 256, 256>>>(att2, bias2, out);
}